// round 6
// baseline (speedup 1.0000x reference)
#include <cuda_runtime.h>
#include <math.h>

// ---------------- problem constants ----------------
#define VSZ   32000
#define ESZ   512            // E = 512 (embedding dim) — NOT 1024!
#define HSZ   1024
#define TXN   2048
#define TYN   512
#define G4    4096           // 4*H

// ---------------- device scratch (no allocs allowed) ----------------
__device__ float g_G[(size_t)TXN * G4];      // Wih@x + b, all timesteps (33.5MB)
__device__ float g_seq[(size_t)TXN * HSZ];   // layer0 outputs (8.4MB)
__device__ float g_h[2][HSZ];                // encoder h double buffer
__device__ float g_hlast[HSZ];
__device__ float g_f1[HSZ];
__device__ float g_hinit[HSZ];               // f2 -> decoder h/c init
__device__ float g_d0[2][HSZ];               // decoder layer0 h
__device__ float g_d1[2][HSZ];               // decoder layer1 h
__device__ unsigned long long g_amax[TYN - 1];
__device__ unsigned int g_bars[4];

// ---------------- helpers ----------------
__device__ __forceinline__ double wredsum_d(double v) {
#pragma unroll
    for (int o = 16; o; o >>= 1) v += __shfl_xor_sync(0xffffffffu, v, o);
    return v;
}

// Gate evaluation split across lanes 0..3 in fp64.
__device__ __forceinline__ void gates4_d(double a0, double a1, double a2, double a3,
                                         double addv, int lane,
                                         double& i_, double& f_, double& g_, double& o_) {
    double asel = (lane == 0) ? a0 : (lane == 1) ? a1 : (lane == 2) ? a2 : a3;
    double gv = 0.0;
    if (lane < 4) {
        double xd = asel + addv;
        gv = (lane == 2) ? tanh(xd) : (1.0 / (1.0 + exp(-xd)));
    }
    i_ = __shfl_sync(0xffffffffu, gv, 0);
    f_ = __shfl_sync(0xffffffffu, gv, 1);
    g_ = __shfl_sync(0xffffffffu, gv, 2);
    o_ = __shfl_sync(0xffffffffu, gv, 3);
}

// Software grid barrier: all blocks must be co-resident (grid <= #SMs, occ>=1).
__device__ __forceinline__ void gbar(unsigned int* cnt, unsigned int& epoch) {
    epoch += gridDim.x;
    __threadfence();
    __syncthreads();
    if (threadIdx.x == 0) {
        atomicAdd(cnt, 1);
        while (*(volatile unsigned int*)cnt < epoch) { }
    }
    __syncthreads();
}

// ---------------- init ----------------
__global__ void init_kernel() {
    int i = threadIdx.x;
    if (i < 4) g_bars[i] = 0u;
    for (int j = i; j < TYN - 1; j += blockDim.x) g_amax[j] = 0ull;
}

// ---------------- tiled GEMM (fp32 products, fp64 accumulate) ----------------
// C[m][n] = sum_{k<KDIM} A'[m][k]*B[n][k] + bias[n]
// A'[m] = A + (ridx? ridx[m] : m)*KDIM (row stride KDIM). B row stride KDIM.
// M=2048, N=4096. KDIM = 512 (layer0: emb/eWih0) or 1024 (layer1: seq/eWih1).
template <int KDIM>
__global__ void gemm_nt(const float* __restrict__ A, const int* __restrict__ ridx,
                        const float* __restrict__ B, const float* __restrict__ bias,
                        float* __restrict__ C) {
    __shared__ float As[64][17];
    __shared__ float Bs[64][17];
    int tid = threadIdx.x;                 // 256 threads
    int m0 = blockIdx.y * 64, n0 = blockIdx.x * 64;
    int tx = tid & 15, ty = tid >> 4;
    int lrow = tid >> 2;
    int lk4 = (tid & 3) * 4;
    const float* arow = A + (size_t)(ridx ? ridx[m0 + lrow] : (m0 + lrow)) * KDIM;
    const float* brow = B + (size_t)(n0 + lrow) * KDIM;
    double acc[4][4] = {};
    for (int kb = 0; kb < KDIM; kb += 16) {
        float4 av = *(const float4*)(arow + kb + lk4);
        float4 bv = *(const float4*)(brow + kb + lk4);
        __syncthreads();
        As[lrow][lk4 + 0] = av.x; As[lrow][lk4 + 1] = av.y;
        As[lrow][lk4 + 2] = av.z; As[lrow][lk4 + 3] = av.w;
        Bs[lrow][lk4 + 0] = bv.x; Bs[lrow][lk4 + 1] = bv.y;
        Bs[lrow][lk4 + 2] = bv.z; Bs[lrow][lk4 + 3] = bv.w;
        __syncthreads();
        float part[4][4];
#pragma unroll
        for (int i = 0; i < 4; i++)
#pragma unroll
            for (int j = 0; j < 4; j++) part[i][j] = 0.0f;
#pragma unroll
        for (int kk = 0; kk < 16; kk++) {
            float a[4], b[4];
#pragma unroll
            for (int i = 0; i < 4; i++) a[i] = As[ty * 4 + i][kk];
#pragma unroll
            for (int j = 0; j < 4; j++) b[j] = Bs[tx * 4 + j][kk];
#pragma unroll
            for (int i = 0; i < 4; i++)
#pragma unroll
                for (int j = 0; j < 4; j++) part[i][j] += a[i] * b[j];
        }
#pragma unroll
        for (int i = 0; i < 4; i++)
#pragma unroll
            for (int j = 0; j < 4; j++) acc[i][j] += (double)part[i][j];
    }
#pragma unroll
    for (int i = 0; i < 4; i++)
#pragma unroll
        for (int j = 0; j < 4; j++)
            C[(size_t)(m0 + ty * 4 + i) * G4 + n0 + tx * 4 + j] =
                (float)(acc[i][j] + (double)__ldg(bias + n0 + tx * 4 + j));
}

// ---------------- persistent encoder LSTM scan (Whh resident in SMEM) ----------------
// grid = 128 blocks x 256 threads. warp w of block b owns hidden unit b*8+w.
#define ENC_SMEM ((8 * 4 * 1024 + 1024) * 4)
template <int WRITE_SEQ, int WRITE_LAST, int BARIDX>
__global__ void enc_scan(const float* __restrict__ Whh, const float* __restrict__ G,
                         float* __restrict__ seq) {
    extern __shared__ float sm[];
    float* sW = sm;                 // 8 units * 4 rows * 1024
    float* sh = sm + 8 * 4 * 1024;  // staged h (1024)
    int tid = threadIdx.x, wid = tid >> 5, lane = tid & 31;
    int unit = blockIdx.x * 8 + wid;   // 0..1023
    float* wdst = sW + wid * 4096;
#pragma unroll
    for (int r = 0; r < 4; r++) {
        const float* src = Whh + (size_t)(unit + r * 1024) * 1024;
#pragma unroll
        for (int e = lane * 4; e < 1024; e += 128)
            *(float4*)(wdst + r * 1024 + e) = __ldg((const float4*)(src + e));
    }
    if (blockIdx.x == 0)
        for (int i = tid; i < HSZ; i += blockDim.x) g_h[0][i] = 0.0f;
    unsigned int epoch = 0;
    unsigned int* bar = &g_bars[BARIDX];
    gbar(bar, epoch);
    float c = 0.0f;
    int cur = 0;
    for (int t = 0; t < TXN; t++) {
        *(float4*)(sh + tid * 4) = __ldcg((const float4*)(&g_h[cur][tid * 4]));
        __syncthreads();
        double a0 = 0, a1 = 0, a2 = 0, a3 = 0;
#pragma unroll
        for (int k = 0; k < 8; k++) {
            int j = (k * 32 + lane) << 2;
            float4 h4 = *(float4*)(sh + j);
            float4 w0 = *(float4*)(wdst + j);
            float4 w1 = *(float4*)(wdst + 1024 + j);
            float4 w2 = *(float4*)(wdst + 2048 + j);
            float4 w3 = *(float4*)(wdst + 3072 + j);
            a0 += (double)(w0.x * h4.x + w0.y * h4.y) + (double)(w0.z * h4.z + w0.w * h4.w);
            a1 += (double)(w1.x * h4.x + w1.y * h4.y) + (double)(w1.z * h4.z + w1.w * h4.w);
            a2 += (double)(w2.x * h4.x + w2.y * h4.y) + (double)(w2.z * h4.z + w2.w * h4.w);
            a3 += (double)(w3.x * h4.x + w3.y * h4.y) + (double)(w3.z * h4.z + w3.w * h4.w);
        }
        a0 = wredsum_d(a0); a1 = wredsum_d(a1); a2 = wredsum_d(a2); a3 = wredsum_d(a3);
        const float* gt = G + (size_t)t * G4;
        double addv = 0.0;
        if (lane < 4) addv = (double)__ldg(gt + unit + lane * 1024);
        double i_, f_, gg, o_;
        gates4_d(a0, a1, a2, a3, addv, lane, i_, f_, gg, o_);
        if (lane == 0) {
            c = (float)(f_ * (double)c + i_ * gg);
            float h = (float)(o_ * tanh((double)c));
            g_h[cur ^ 1][unit] = h;
            if (WRITE_SEQ) seq[(size_t)t * HSZ + unit] = h;
            if (WRITE_LAST && t == TXN - 1) g_hlast[unit] = h;
        }
        gbar(bar, epoch);
        cur ^= 1;
    }
}

// ---------------- fc + relu: one block per output row (fp64 accumulate) ----------------
__global__ void fc_relu(const float* __restrict__ W, const float* __restrict__ b,
                        const float* __restrict__ in, float* __restrict__ out) {
    __shared__ double red[8];
    int r = blockIdx.x, tid = threadIdx.x, wid = tid >> 5, lane = tid & 31;
    const float* wr = W + (size_t)r * 1024;
    float4 w = __ldg((const float4*)(wr + tid * 4));
    float4 v = __ldg((const float4*)(in + tid * 4));
    double acc = (double)(w.x * v.x) + (double)(w.y * v.y) +
                 (double)(w.z * v.z) + (double)(w.w * v.w);
    acc = wredsum_d(acc);
    if (lane == 0) red[wid] = acc;
    __syncthreads();
    if (tid == 0) {
        double s = 0;
#pragma unroll
        for (int i = 0; i < 8; i++) s += red[i];
        double val = s + (double)__ldg(b + r);
        out[r] = (float)(val > 0.0 ? val : 0.0);
    }
}

// ---------------- persistent greedy decoder ----------------
__global__ void decoder_kernel(
    const float* __restrict__ dWih0, const float* __restrict__ dWhh0, const float* __restrict__ db0,
    const float* __restrict__ dWih1, const float* __restrict__ dWhh1, const float* __restrict__ db1,
    const float* __restrict__ outw, const float* __restrict__ outb,
    const int* __restrict__ y, float* __restrict__ out) {
    __shared__ float sh0[HSZ];
    __shared__ float sh1[HSZ];
    __shared__ unsigned long long skeys[8];
    int tid = threadIdx.x, wid = tid >> 5, lane = tid & 31;
    int unit = blockIdx.x * 8 + wid;
    unsigned int epoch = 0;
    unsigned int* bar = &g_bars[2];
    if (blockIdx.x == 0)
        for (int i = tid; i < HSZ; i += blockDim.x) {
            float v = g_hinit[i];
            g_d0[0][i] = v; g_d1[0][i] = v;
        }
    float c0 = 0.0f, c1 = 0.0f;
    if (unit < HSZ) { c0 = __ldg(&g_hinit[unit]); c1 = c0; }
    gbar(bar, epoch);
    int cur = 0;
    float xt0 = (float)__ldg(&y[0]);
    int gw = blockIdx.x * 8 + wid, nw = gridDim.x * 8;

    for (int t = 0; t < TYN - 1; t++) {
        float xt;
        if (t == 0) xt = xt0;
        else {
            unsigned long long key = __ldcg(&g_amax[t - 1]);
            xt = (float)(0xFFFFFFFFu - (unsigned int)(key & 0xFFFFFFFFull));
        }
        // ---- layer 0 ----
        *(float4*)(sh0 + tid * 4) = __ldcg((const float4*)(&g_d0[cur][tid * 4]));
        __syncthreads();
        if (unit < HSZ) {
            double a0 = 0, a1 = 0, a2 = 0, a3 = 0;
            const float* b = dWhh0 + (size_t)unit * 1024;
#pragma unroll
            for (int k = 0; k < 8; k++) {
                int j = (k * 32 + lane) << 2;
                float4 h4 = *(float4*)(sh0 + j);
                float4 w;
                w = __ldg((const float4*)(b + j));
                a0 += (double)(w.x * h4.x + w.y * h4.y) + (double)(w.z * h4.z + w.w * h4.w);
                w = __ldg((const float4*)(b + (1 << 20) + j));
                a1 += (double)(w.x * h4.x + w.y * h4.y) + (double)(w.z * h4.z + w.w * h4.w);
                w = __ldg((const float4*)(b + (2 << 20) + j));
                a2 += (double)(w.x * h4.x + w.y * h4.y) + (double)(w.z * h4.z + w.w * h4.w);
                w = __ldg((const float4*)(b + (3 << 20) + j));
                a3 += (double)(w.x * h4.x + w.y * h4.y) + (double)(w.z * h4.z + w.w * h4.w);
            }
            a0 = wredsum_d(a0); a1 = wredsum_d(a1); a2 = wredsum_d(a2); a3 = wredsum_d(a3);
            double addv = 0.0;
            if (lane < 4)
                addv = (double)__ldg(dWih0 + unit + lane * 1024) * (double)xt +
                       (double)__ldg(db0 + unit + lane * 1024);
            double i_, f_, gg, o_;
            gates4_d(a0, a1, a2, a3, addv, lane, i_, f_, gg, o_);
            if (lane == 0) {
                c0 = (float)(f_ * (double)c0 + i_ * gg);
                g_d0[cur ^ 1][unit] = (float)(o_ * tanh((double)c0));
            }
        }
        gbar(bar, epoch);
        // ---- layer 1 ----
        *(float4*)(sh0 + tid * 4) = __ldcg((const float4*)(&g_d0[cur ^ 1][tid * 4]));
        *(float4*)(sh1 + tid * 4) = __ldcg((const float4*)(&g_d1[cur][tid * 4]));
        __syncthreads();
        if (unit < HSZ) {
            double a0 = 0, a1 = 0, a2 = 0, a3 = 0;
            const float* bi = dWih1 + (size_t)unit * 1024;
            const float* bh = dWhh1 + (size_t)unit * 1024;
#pragma unroll
            for (int k = 0; k < 8; k++) {
                int j = (k * 32 + lane) << 2;
                float4 ha = *(float4*)(sh0 + j);
                float4 hb = *(float4*)(sh1 + j);
                float4 w;
                w = __ldg((const float4*)(bi + j));
                a0 += (double)(w.x * ha.x + w.y * ha.y) + (double)(w.z * ha.z + w.w * ha.w);
                w = __ldg((const float4*)(bh + j));
                a0 += (double)(w.x * hb.x + w.y * hb.y) + (double)(w.z * hb.z + w.w * hb.w);
                w = __ldg((const float4*)(bi + (1 << 20) + j));
                a1 += (double)(w.x * ha.x + w.y * ha.y) + (double)(w.z * ha.z + w.w * ha.w);
                w = __ldg((const float4*)(bh + (1 << 20) + j));
                a1 += (double)(w.x * hb.x + w.y * hb.y) + (double)(w.z * hb.z + w.w * hb.w);
                w = __ldg((const float4*)(bi + (2 << 20) + j));
                a2 += (double)(w.x * ha.x + w.y * ha.y) + (double)(w.z * ha.z + w.w * ha.w);
                w = __ldg((const float4*)(bh + (2 << 20) + j));
                a2 += (double)(w.x * hb.x + w.y * hb.y) + (double)(w.z * hb.z + w.w * hb.w);
                w = __ldg((const float4*)(bi + (3 << 20) + j));
                a3 += (double)(w.x * ha.x + w.y * ha.y) + (double)(w.z * ha.z + w.w * ha.w);
                w = __ldg((const float4*)(bh + (3 << 20) + j));
                a3 += (double)(w.x * hb.x + w.y * hb.y) + (double)(w.z * hb.z + w.w * hb.w);
            }
            a0 = wredsum_d(a0); a1 = wredsum_d(a1); a2 = wredsum_d(a2); a3 = wredsum_d(a3);
            double addv = 0.0;
            if (lane < 4) addv = (double)__ldg(db1 + unit + lane * 1024);
            double i_, f_, gg, o_;
            gates4_d(a0, a1, a2, a3, addv, lane, i_, f_, gg, o_);
            if (lane == 0) {
                c1 = (float)(f_ * (double)c1 + i_ * gg);
                g_d1[cur ^ 1][unit] = (float)(o_ * tanh((double)c1));
            }
        }
        gbar(bar, epoch);
        // ---- projection + argmax (fp64 accumulation of fp32 pair-products) ----
        *(float4*)(sh1 + tid * 4) = __ldcg((const float4*)(&g_d1[cur ^ 1][tid * 4]));
        __syncthreads();
        double bestv = -1e300; int besti = 0;
        float* orow = out + (size_t)(t + 1) * VSZ;
        for (int r = gw; r < VSZ; r += nw) {
            const float* wr = outw + (size_t)r * 1024;
            double acc = 0;
#pragma unroll
            for (int k = 0; k < 8; k++) {
                int j = (k * 32 + lane) << 2;
                float4 w = __ldcs((const float4*)(wr + j));   // streaming: keep LSTM wts in L2
                float4 h4 = *(float4*)(sh1 + j);
                acc += (double)(w.x * h4.x + w.y * h4.y) + (double)(w.z * h4.z + w.w * h4.w);
            }
            acc = wredsum_d(acc);
            if (lane == 0) {
                double lg = acc + (double)__ldg(outb + r);
                orow[r] = (float)lg;
                if (lg > bestv) { bestv = lg; besti = r; }
            }
        }
        if (lane == 0) {
            unsigned int u = __float_as_uint((float)bestv);
            u = (u & 0x80000000u) ? ~u : (u | 0x80000000u);
            skeys[wid] = ((unsigned long long)u << 32) |
                         (unsigned long long)(0xFFFFFFFFu - (unsigned int)besti);
        }
        __syncthreads();
        if (tid == 0) {
            unsigned long long k0 = skeys[0];
#pragma unroll
            for (int w = 1; w < 8; w++) if (skeys[w] > k0) k0 = skeys[w];
            atomicMax(&g_amax[t], k0);
        }
        gbar(bar, epoch);
        cur ^= 1;
    }
}

// ---------------- final log_softmax over rows (in place) ----------------
__global__ void logsoftmax_kernel(float* __restrict__ out) {
    int row = blockIdx.x, tid = threadIdx.x, wid = tid >> 5, lane = tid & 31;
    float* p = out + (size_t)row * VSZ;
    if (row == 0) {
        float v = -(float)log((double)VSZ);
        for (int i = tid; i < VSZ; i += blockDim.x) p[i] = v;
        return;
    }
    __shared__ double redd[8];
    __shared__ float redf[8];
    __shared__ float bcf;
    __shared__ double bcd;
    float m = -INFINITY;
    for (int i = tid; i < VSZ; i += blockDim.x) m = fmaxf(m, p[i]);
#pragma unroll
    for (int o = 16; o; o >>= 1) m = fmaxf(m, __shfl_xor_sync(0xffffffffu, m, o));
    if (lane == 0) redf[wid] = m;
    __syncthreads();
    if (tid == 0) {
        float mm = redf[0];
#pragma unroll
        for (int i = 1; i < 8; i++) mm = fmaxf(mm, redf[i]);
        bcf = mm;
    }
    __syncthreads();
    m = bcf;
    double s = 0;
    for (int i = tid; i < VSZ; i += blockDim.x) s += exp((double)(p[i] - m));
    s = wredsum_d(s);
    if (lane == 0) redd[wid] = s;
    __syncthreads();
    if (tid == 0) {
        double ss = 0;
#pragma unroll
        for (int i = 0; i < 8; i++) ss += redd[i];
        bcd = (double)m + log(ss);
    }
    __syncthreads();
    double lse = bcd;
    for (int i = tid; i < VSZ; i += blockDim.x) p[i] = (float)((double)p[i] - lse);
}

// ---------------- launch ----------------
extern "C" void kernel_launch(void* const* d_in, const int* in_sizes, int n_in,
                              void* d_out, int out_size) {
    const int*   x     = (const int*)d_in[0];
    const int*   y     = (const int*)d_in[1];
    const float* emb   = (const float*)d_in[2];
    const float* eWih0 = (const float*)d_in[3];
    const float* eWhh0 = (const float*)d_in[4];
    const float* eb0   = (const float*)d_in[5];
    const float* eWih1 = (const float*)d_in[6];
    const float* eWhh1 = (const float*)d_in[7];
    const float* eb1   = (const float*)d_in[8];
    const float* fc1w  = (const float*)d_in[9];
    const float* fc1b  = (const float*)d_in[10];
    const float* fc2w  = (const float*)d_in[11];
    const float* fc2b  = (const float*)d_in[12];
    const float* dWih0 = (const float*)d_in[13];
    const float* dWhh0 = (const float*)d_in[14];
    const float* db0   = (const float*)d_in[15];
    const float* dWih1 = (const float*)d_in[16];
    const float* dWhh1 = (const float*)d_in[17];
    const float* db1   = (const float*)d_in[18];
    const float* outw  = (const float*)d_in[19];
    const float* outb  = (const float*)d_in[20];
    float* out = (float*)d_out;

    float *pG = nullptr, *pSeq = nullptr, *pF1 = nullptr, *pHinit = nullptr, *pHlast = nullptr;
    cudaGetSymbolAddress((void**)&pG, g_G);
    cudaGetSymbolAddress((void**)&pSeq, g_seq);
    cudaGetSymbolAddress((void**)&pF1, g_f1);
    cudaGetSymbolAddress((void**)&pHinit, g_hinit);
    cudaGetSymbolAddress((void**)&pHlast, g_hlast);

    int dev = 0, nsm = 148;
    cudaGetDevice(&dev);
    cudaDeviceGetAttribute(&nsm, cudaDevAttrMultiProcessorCount, dev);
    if (nsm < 128) nsm = 128;

    cudaFuncSetAttribute(enc_scan<1, 0, 0>, cudaFuncAttributeMaxDynamicSharedMemorySize, ENC_SMEM);
    cudaFuncSetAttribute(enc_scan<0, 1, 1>, cudaFuncAttributeMaxDynamicSharedMemorySize, ENC_SMEM);

    init_kernel<<<1, 512>>>();
    // G0 = gather(emb, x) @ Wih0^T + b0   --- K = E = 512 !
    gemm_nt<ESZ><<<dim3(64, 32), 256>>>(emb, x, eWih0, eb0, pG);
    // layer-0 scan (writes g_seq)
    enc_scan<1, 0, 0><<<128, 256, ENC_SMEM>>>(eWhh0, pG, pSeq);
    // G1 = g_seq @ Wih1^T + b1            --- K = H = 1024
    gemm_nt<HSZ><<<dim3(64, 32), 256>>>(pSeq, nullptr, eWih1, eb1, pG);
    // layer-1 scan (writes g_hlast)
    enc_scan<0, 1, 1><<<128, 256, ENC_SMEM>>>(eWhh1, pG, nullptr);
    // bridge MLP
    fc_relu<<<1024, 256>>>(fc1w, fc1b, pHlast, pF1);
    fc_relu<<<1024, 256>>>(fc2w, fc2b, pF1, pHinit);
    // greedy decoder (writes raw logits into out rows 1..511)
    decoder_kernel<<<nsm, 256>>>(dWih0, dWhh0, db0, dWih1, dWhh1, db1, outw, outb, y, out);
    // final log_softmax (+ row 0 constant)
    logsoftmax_kernel<<<TYN, 256>>>(out);
}

// round 7
// speedup vs baseline: 1.5793x; 1.5793x over previous
#include <cuda_runtime.h>
#include <math.h>

// ---------------- problem constants ----------------
#define VSZ   32000
#define ESZ   512            // E = 512 (embedding dim)
#define HSZ   1024
#define TXN   2048
#define TYN   512
#define G4    4096           // 4*H

// ---------------- device scratch (no allocs allowed) ----------------
__device__ float g_G[(size_t)TXN * G4];
__device__ float g_seq[(size_t)TXN * HSZ];
__device__ float g_h[2][HSZ];
__device__ float g_hlast[HSZ];
__device__ float g_f1[HSZ];
__device__ float g_hinit[HSZ];
__device__ float g_d0[2][HSZ];
__device__ float g_d1[2][HSZ];
__device__ unsigned long long g_amax[TYN - 1];
__device__ unsigned int g_bars[4];

// ---------------- helpers ----------------
__device__ __forceinline__ double wredsum_d(double v) {
#pragma unroll
    for (int o = 16; o; o >>= 1) v += __shfl_xor_sync(0xffffffffu, v, o);
    return v;
}

// fp32 gate eval on lanes 0..3 (accurate expf/tanhf; harness is NOT fast-math),
// pre-activation summed in fp64, rounded once to fp32 before the nonlinearity.
__device__ __forceinline__ void gates4_f(double a0, double a1, double a2, double a3,
                                         float addv, int lane,
                                         float& i_, float& f_, float& g_, float& o_) {
    double asel = (lane == 0) ? a0 : (lane == 1) ? a1 : (lane == 2) ? a2 : a3;
    float gv = 0.0f;
    if (lane < 4) {
        float x = (float)(asel + (double)addv);
        gv = (lane == 2) ? tanhf(x) : 1.0f / (1.0f + expf(-x));
    }
    i_ = __shfl_sync(0xffffffffu, gv, 0);
    f_ = __shfl_sync(0xffffffffu, gv, 1);
    g_ = __shfl_sync(0xffffffffu, gv, 2);
    o_ = __shfl_sync(0xffffffffu, gv, 3);
}

// Software grid barrier (all blocks co-resident).
__device__ __forceinline__ void gbar(unsigned int* cnt, unsigned int& epoch) {
    epoch += gridDim.x;
    __threadfence();
    __syncthreads();
    if (threadIdx.x == 0) {
        atomicAdd(cnt, 1);
        while (*(volatile unsigned int*)cnt < epoch) { }
    }
    __syncthreads();
}

// ---------------- init ----------------
__global__ void init_kernel() {
    int i = threadIdx.x;
    if (i < 4) g_bars[i] = 0u;
    for (int j = i; j < TYN - 1; j += blockDim.x) g_amax[j] = 0ull;
}

// ---------------- tiled GEMM (fp32 products, fp64 accumulate) ----------------
template <int KDIM>
__global__ void gemm_nt(const float* __restrict__ A, const int* __restrict__ ridx,
                        const float* __restrict__ B, const float* __restrict__ bias,
                        float* __restrict__ C) {
    __shared__ float As[64][17];
    __shared__ float Bs[64][17];
    int tid = threadIdx.x;
    int m0 = blockIdx.y * 64, n0 = blockIdx.x * 64;
    int tx = tid & 15, ty = tid >> 4;
    int lrow = tid >> 2;
    int lk4 = (tid & 3) * 4;
    const float* arow = A + (size_t)(ridx ? ridx[m0 + lrow] : (m0 + lrow)) * KDIM;
    const float* brow = B + (size_t)(n0 + lrow) * KDIM;
    double acc[4][4] = {};
    for (int kb = 0; kb < KDIM; kb += 16) {
        float4 av = *(const float4*)(arow + kb + lk4);
        float4 bv = *(const float4*)(brow + kb + lk4);
        __syncthreads();
        As[lrow][lk4 + 0] = av.x; As[lrow][lk4 + 1] = av.y;
        As[lrow][lk4 + 2] = av.z; As[lrow][lk4 + 3] = av.w;
        Bs[lrow][lk4 + 0] = bv.x; Bs[lrow][lk4 + 1] = bv.y;
        Bs[lrow][lk4 + 2] = bv.z; Bs[lrow][lk4 + 3] = bv.w;
        __syncthreads();
        float part[4][4];
#pragma unroll
        for (int i = 0; i < 4; i++)
#pragma unroll
            for (int j = 0; j < 4; j++) part[i][j] = 0.0f;
#pragma unroll
        for (int kk = 0; kk < 16; kk++) {
            float a[4], b[4];
#pragma unroll
            for (int i = 0; i < 4; i++) a[i] = As[ty * 4 + i][kk];
#pragma unroll
            for (int j = 0; j < 4; j++) b[j] = Bs[tx * 4 + j][kk];
#pragma unroll
            for (int i = 0; i < 4; i++)
#pragma unroll
                for (int j = 0; j < 4; j++) part[i][j] += a[i] * b[j];
        }
#pragma unroll
        for (int i = 0; i < 4; i++)
#pragma unroll
            for (int j = 0; j < 4; j++) acc[i][j] += (double)part[i][j];
    }
#pragma unroll
    for (int i = 0; i < 4; i++)
#pragma unroll
        for (int j = 0; j < 4; j++)
            C[(size_t)(m0 + ty * 4 + i) * G4 + n0 + tx * 4 + j] =
                (float)(acc[i][j] + (double)__ldg(bias + n0 + tx * 4 + j));
}

// ---------------- persistent encoder LSTM scan (Whh in SMEM) ----------------
#define ENC_SMEM ((8 * 4 * 1024 + 1024) * 4)
template <int WRITE_SEQ, int WRITE_LAST, int BARIDX>
__global__ void __launch_bounds__(256, 1)
enc_scan(const float* __restrict__ Whh, const float* __restrict__ G,
         float* __restrict__ seq) {
    extern __shared__ float sm[];
    float* sW = sm;
    float* sh = sm + 8 * 4 * 1024;
    int tid = threadIdx.x, wid = tid >> 5, lane = tid & 31;
    int unit = blockIdx.x * 8 + wid;
    float* wdst = sW + wid * 4096;
#pragma unroll
    for (int r = 0; r < 4; r++) {
        const float* src = Whh + (size_t)(unit + r * 1024) * 1024;
#pragma unroll
        for (int e = lane * 4; e < 1024; e += 128)
            *(float4*)(wdst + r * 1024 + e) = __ldg((const float4*)(src + e));
    }
    if (blockIdx.x == 0)
        for (int i = tid; i < HSZ; i += blockDim.x) g_h[0][i] = 0.0f;
    unsigned int epoch = 0;
    unsigned int* bar = &g_bars[BARIDX];
    gbar(bar, epoch);
    float c = 0.0f;
    int cur = 0;
    for (int t = 0; t < TXN; t++) {
        *(float4*)(sh + tid * 4) = __ldcg((const float4*)(&g_h[cur][tid * 4]));
        __syncthreads();
        // fp32 4-product partial per gate per iter, single DADD per iter (chain 8)
        double a0 = 0, a1 = 0, a2 = 0, a3 = 0;
#pragma unroll
        for (int k = 0; k < 8; k++) {
            int j = (k * 32 + lane) << 2;
            float4 h4 = *(float4*)(sh + j);
            float4 w0 = *(float4*)(wdst + j);
            float4 w1 = *(float4*)(wdst + 1024 + j);
            float4 w2 = *(float4*)(wdst + 2048 + j);
            float4 w3 = *(float4*)(wdst + 3072 + j);
            a0 += (double)(w0.x * h4.x + w0.y * h4.y + w0.z * h4.z + w0.w * h4.w);
            a1 += (double)(w1.x * h4.x + w1.y * h4.y + w1.z * h4.z + w1.w * h4.w);
            a2 += (double)(w2.x * h4.x + w2.y * h4.y + w2.z * h4.z + w2.w * h4.w);
            a3 += (double)(w3.x * h4.x + w3.y * h4.y + w3.z * h4.z + w3.w * h4.w);
        }
        a0 = wredsum_d(a0); a1 = wredsum_d(a1); a2 = wredsum_d(a2); a3 = wredsum_d(a3);
        const float* gt = G + (size_t)t * G4;
        float addv = 0.0f;
        if (lane < 4) addv = __ldg(gt + unit + lane * 1024);
        float i_, f_, gg, o_;
        gates4_f(a0, a1, a2, a3, addv, lane, i_, f_, gg, o_);
        if (lane == 0) {
            c = (float)((double)f_ * (double)c + (double)i_ * (double)gg);
            float h = o_ * tanhf(c);
            g_h[cur ^ 1][unit] = h;
            if (WRITE_SEQ) seq[(size_t)t * HSZ + unit] = h;
            if (WRITE_LAST && t == TXN - 1) g_hlast[unit] = h;
        }
        gbar(bar, epoch);
        cur ^= 1;
    }
}

// ---------------- fc + relu ----------------
__global__ void fc_relu(const float* __restrict__ W, const float* __restrict__ b,
                        const float* __restrict__ in, float* __restrict__ out) {
    __shared__ double red[8];
    int r = blockIdx.x, tid = threadIdx.x, wid = tid >> 5, lane = tid & 31;
    const float* wr = W + (size_t)r * 1024;
    float4 w = __ldg((const float4*)(wr + tid * 4));
    float4 v = __ldg((const float4*)(in + tid * 4));
    double acc = (double)(w.x * v.x) + (double)(w.y * v.y) +
                 (double)(w.z * v.z) + (double)(w.w * v.w);
    acc = wredsum_d(acc);
    if (lane == 0) red[wid] = acc;
    __syncthreads();
    if (tid == 0) {
        double s = 0;
#pragma unroll
        for (int i = 0; i < 8; i++) s += red[i];
        double val = s + (double)__ldg(b + r);
        out[r] = (float)(val > 0.0 ? val : 0.0);
    }
}

// ---------------- persistent greedy decoder (512 threads/block) ----------------
#define DECT 512
__global__ void __launch_bounds__(DECT, 1)
decoder_kernel(
    const float* __restrict__ dWih0, const float* __restrict__ dWhh0, const float* __restrict__ db0,
    const float* __restrict__ dWih1, const float* __restrict__ dWhh1, const float* __restrict__ db1,
    const float* __restrict__ outw, const float* __restrict__ outb,
    const int* __restrict__ y, float* __restrict__ out) {
    __shared__ float sh0[HSZ];
    __shared__ float sh1[HSZ];
    __shared__ unsigned long long skeys[16];
    int tid = threadIdx.x, wid = tid >> 5, lane = tid & 31;
    int unit = blockIdx.x * 16 + wid;           // layer work: units 0..1023
    unsigned int epoch = 0;
    unsigned int* bar = &g_bars[2];
    if (blockIdx.x == 0)
        for (int i = tid; i < HSZ; i += blockDim.x) {
            float v = g_hinit[i];
            g_d0[0][i] = v; g_d1[0][i] = v;
        }
    float c0 = 0.0f, c1 = 0.0f;
    if (unit < HSZ) { c0 = __ldg(&g_hinit[unit]); c1 = c0; }
    gbar(bar, epoch);
    int cur = 0;
    float xt0 = (float)__ldg(&y[0]);
    int gw = blockIdx.x * 16 + wid, nw = gridDim.x * 16;

    for (int t = 0; t < TYN - 1; t++) {
        float xt;
        if (t == 0) xt = xt0;
        else {
            unsigned long long key = __ldcg(&g_amax[t - 1]);
            xt = (float)(0xFFFFFFFFu - (unsigned int)(key & 0xFFFFFFFFull));
        }
        // ---- layer 0 ----
        if (tid < 256)
            *(float4*)(sh0 + tid * 4) = __ldcg((const float4*)(&g_d0[cur][tid * 4]));
        __syncthreads();
        if (unit < HSZ) {
            double a0 = 0, a1 = 0, a2 = 0, a3 = 0;
            const float* b = dWhh0 + (size_t)unit * 1024;
#pragma unroll
            for (int k = 0; k < 8; k++) {
                int j = (k * 32 + lane) << 2;
                float4 h4 = *(float4*)(sh0 + j);
                float4 w;
                w = __ldg((const float4*)(b + j));
                a0 += (double)(w.x * h4.x + w.y * h4.y + w.z * h4.z + w.w * h4.w);
                w = __ldg((const float4*)(b + (1 << 20) + j));
                a1 += (double)(w.x * h4.x + w.y * h4.y + w.z * h4.z + w.w * h4.w);
                w = __ldg((const float4*)(b + (2 << 20) + j));
                a2 += (double)(w.x * h4.x + w.y * h4.y + w.z * h4.z + w.w * h4.w);
                w = __ldg((const float4*)(b + (3 << 20) + j));
                a3 += (double)(w.x * h4.x + w.y * h4.y + w.z * h4.z + w.w * h4.w);
            }
            a0 = wredsum_d(a0); a1 = wredsum_d(a1); a2 = wredsum_d(a2); a3 = wredsum_d(a3);
            float addv = 0.0f;
            if (lane < 4)
                addv = (float)((double)__ldg(dWih0 + unit + lane * 1024) * (double)xt +
                               (double)__ldg(db0 + unit + lane * 1024));
            float i_, f_, gg, o_;
            gates4_f(a0, a1, a2, a3, addv, lane, i_, f_, gg, o_);
            if (lane == 0) {
                c0 = (float)((double)f_ * (double)c0 + (double)i_ * (double)gg);
                g_d0[cur ^ 1][unit] = o_ * tanhf(c0);
            }
        }
        gbar(bar, epoch);
        // ---- layer 1 ----
        if (tid < 256) {
            *(float4*)(sh0 + tid * 4) = __ldcg((const float4*)(&g_d0[cur ^ 1][tid * 4]));
            *(float4*)(sh1 + tid * 4) = __ldcg((const float4*)(&g_d1[cur][tid * 4]));
        }
        __syncthreads();
        if (unit < HSZ) {
            double ai0 = 0, ah0 = 0, ai1 = 0, ah1 = 0, ai2 = 0, ah2 = 0, ai3 = 0, ah3 = 0;
            const float* bi = dWih1 + (size_t)unit * 1024;
            const float* bh = dWhh1 + (size_t)unit * 1024;
#pragma unroll
            for (int k = 0; k < 8; k++) {
                int j = (k * 32 + lane) << 2;
                float4 ha = *(float4*)(sh0 + j);
                float4 hb = *(float4*)(sh1 + j);
                float4 w;
                w = __ldg((const float4*)(bi + j));
                ai0 += (double)(w.x * ha.x + w.y * ha.y + w.z * ha.z + w.w * ha.w);
                w = __ldg((const float4*)(bh + j));
                ah0 += (double)(w.x * hb.x + w.y * hb.y + w.z * hb.z + w.w * hb.w);
                w = __ldg((const float4*)(bi + (1 << 20) + j));
                ai1 += (double)(w.x * ha.x + w.y * ha.y + w.z * ha.z + w.w * ha.w);
                w = __ldg((const float4*)(bh + (1 << 20) + j));
                ah1 += (double)(w.x * hb.x + w.y * hb.y + w.z * hb.z + w.w * hb.w);
                w = __ldg((const float4*)(bi + (2 << 20) + j));
                ai2 += (double)(w.x * ha.x + w.y * ha.y + w.z * ha.z + w.w * ha.w);
                w = __ldg((const float4*)(bh + (2 << 20) + j));
                ah2 += (double)(w.x * hb.x + w.y * hb.y + w.z * hb.z + w.w * hb.w);
                w = __ldg((const float4*)(bi + (3 << 20) + j));
                ai3 += (double)(w.x * ha.x + w.y * ha.y + w.z * ha.z + w.w * ha.w);
                w = __ldg((const float4*)(bh + (3 << 20) + j));
                ah3 += (double)(w.x * hb.x + w.y * hb.y + w.z * hb.z + w.w * hb.w);
            }
            double a0 = wredsum_d(ai0 + ah0);
            double a1 = wredsum_d(ai1 + ah1);
            double a2 = wredsum_d(ai2 + ah2);
            double a3 = wredsum_d(ai3 + ah3);
            float addv = 0.0f;
            if (lane < 4) addv = __ldg(db1 + unit + lane * 1024);
            float i_, f_, gg, o_;
            gates4_f(a0, a1, a2, a3, addv, lane, i_, f_, gg, o_);
            if (lane == 0) {
                c1 = (float)((double)f_ * (double)c1 + (double)i_ * (double)gg);
                g_d1[cur ^ 1][unit] = o_ * tanhf(c1);
            }
        }
        gbar(bar, epoch);
        // ---- projection + argmax (ILP-2 over rows) ----
        if (tid < 256)
            *(float4*)(sh1 + tid * 4) = __ldcg((const float4*)(&g_d1[cur ^ 1][tid * 4]));
        __syncthreads();
        double bestv = -1e300; int besti = 0;
        float* orow = out + (size_t)(t + 1) * VSZ;
        int r = gw;
        for (; r + nw < VSZ; r += 2 * nw) {
            int r2 = r + nw;
            const float* wr0 = outw + (size_t)r * 1024;
            const float* wr1 = outw + (size_t)r2 * 1024;
            double pA0 = 0, pA1 = 0, pB0 = 0, pB1 = 0;
#pragma unroll
            for (int k = 0; k < 8; k += 2) {
                int j0 = (k * 32 + lane) << 2;
                int j1 = ((k + 1) * 32 + lane) << 2;
                float4 wa0 = __ldcs((const float4*)(wr0 + j0));
                float4 wa1 = __ldcs((const float4*)(wr0 + j1));
                float4 wb0 = __ldcs((const float4*)(wr1 + j0));
                float4 wb1 = __ldcs((const float4*)(wr1 + j1));
                float4 h40 = *(float4*)(sh1 + j0);
                float4 h41 = *(float4*)(sh1 + j1);
                pA0 += (double)(wa0.x * h40.x + wa0.y * h40.y + wa0.z * h40.z + wa0.w * h40.w);
                pA1 += (double)(wa1.x * h41.x + wa1.y * h41.y + wa1.z * h41.z + wa1.w * h41.w);
                pB0 += (double)(wb0.x * h40.x + wb0.y * h40.y + wb0.z * h40.z + wb0.w * h40.w);
                pB1 += (double)(wb1.x * h41.x + wb1.y * h41.y + wb1.z * h41.z + wb1.w * h41.w);
            }
            double accA = wredsum_d(pA0 + pA1);
            double accB = wredsum_d(pB0 + pB1);
            if (lane == 0) {
                double lgA = accA + (double)__ldg(outb + r);
                double lgB = accB + (double)__ldg(outb + r2);
                orow[r] = (float)lgA;
                orow[r2] = (float)lgB;
                if (lgA > bestv) { bestv = lgA; besti = r; }
                if (lgB > bestv) { bestv = lgB; besti = r2; }
            }
        }
        if (r < VSZ) {
            const float* wr0 = outw + (size_t)r * 1024;
            double p0 = 0, p1 = 0;
#pragma unroll
            for (int k = 0; k < 8; k += 2) {
                int j0 = (k * 32 + lane) << 2;
                int j1 = ((k + 1) * 32 + lane) << 2;
                float4 wa0 = __ldcs((const float4*)(wr0 + j0));
                float4 wa1 = __ldcs((const float4*)(wr0 + j1));
                float4 h40 = *(float4*)(sh1 + j0);
                float4 h41 = *(float4*)(sh1 + j1);
                p0 += (double)(wa0.x * h40.x + wa0.y * h40.y + wa0.z * h40.z + wa0.w * h40.w);
                p1 += (double)(wa1.x * h41.x + wa1.y * h41.y + wa1.z * h41.z + wa1.w * h41.w);
            }
            double acc = wredsum_d(p0 + p1);
            if (lane == 0) {
                double lg = acc + (double)__ldg(outb + r);
                orow[r] = (float)lg;
                if (lg > bestv) { bestv = lg; besti = r; }
            }
        }
        if (lane == 0) {
            unsigned int u = __float_as_uint((float)bestv);
            u = (u & 0x80000000u) ? ~u : (u | 0x80000000u);
            skeys[wid] = ((unsigned long long)u << 32) |
                         (unsigned long long)(0xFFFFFFFFu - (unsigned int)besti);
        }
        __syncthreads();
        if (tid == 0) {
            unsigned long long k0 = skeys[0];
#pragma unroll
            for (int w = 1; w < 16; w++) if (skeys[w] > k0) k0 = skeys[w];
            atomicMax(&g_amax[t], k0);
        }
        gbar(bar, epoch);
        cur ^= 1;
    }
}

// ---------------- final log_softmax over rows (in place) ----------------
__global__ void logsoftmax_kernel(float* __restrict__ out) {
    int row = blockIdx.x, tid = threadIdx.x, wid = tid >> 5, lane = tid & 31;
    float* p = out + (size_t)row * VSZ;
    if (row == 0) {
        float v = -(float)log((double)VSZ);
        for (int i = tid; i < VSZ; i += blockDim.x) p[i] = v;
        return;
    }
    __shared__ double redd[8];
    __shared__ float redf[8];
    __shared__ float bcf;
    __shared__ double bcd;
    float m = -INFINITY;
    for (int i = tid; i < VSZ; i += blockDim.x) m = fmaxf(m, p[i]);
#pragma unroll
    for (int o = 16; o; o >>= 1) m = fmaxf(m, __shfl_xor_sync(0xffffffffu, m, o));
    if (lane == 0) redf[wid] = m;
    __syncthreads();
    if (tid == 0) {
        float mm = redf[0];
#pragma unroll
        for (int i = 1; i < 8; i++) mm = fmaxf(mm, redf[i]);
        bcf = mm;
    }
    __syncthreads();
    m = bcf;
    double s = 0;
    for (int i = tid; i < VSZ; i += blockDim.x) s += (double)expf(p[i] - m);
    s = wredsum_d(s);
    if (lane == 0) redd[wid] = s;
    __syncthreads();
    if (tid == 0) {
        double ss = 0;
#pragma unroll
        for (int i = 0; i < 8; i++) ss += redd[i];
        bcd = (double)m + log(ss);
    }
    __syncthreads();
    double lse = bcd;
    for (int i = tid; i < VSZ; i += blockDim.x) p[i] = (float)((double)p[i] - lse);
}

// ---------------- launch ----------------
extern "C" void kernel_launch(void* const* d_in, const int* in_sizes, int n_in,
                              void* d_out, int out_size) {
    const int*   x     = (const int*)d_in[0];
    const int*   y     = (const int*)d_in[1];
    const float* emb   = (const float*)d_in[2];
    const float* eWih0 = (const float*)d_in[3];
    const float* eWhh0 = (const float*)d_in[4];
    const float* eb0   = (const float*)d_in[5];
    const float* eWih1 = (const float*)d_in[6];
    const float* eWhh1 = (const float*)d_in[7];
    const float* eb1   = (const float*)d_in[8];
    const float* fc1w  = (const float*)d_in[9];
    const float* fc1b  = (const float*)d_in[10];
    const float* fc2w  = (const float*)d_in[11];
    const float* fc2b  = (const float*)d_in[12];
    const float* dWih0 = (const float*)d_in[13];
    const float* dWhh0 = (const float*)d_in[14];
    const float* db0   = (const float*)d_in[15];
    const float* dWih1 = (const float*)d_in[16];
    const float* dWhh1 = (const float*)d_in[17];
    const float* db1   = (const float*)d_in[18];
    const float* outw  = (const float*)d_in[19];
    const float* outb  = (const float*)d_in[20];
    float* out = (float*)d_out;

    float *pG = nullptr, *pSeq = nullptr, *pF1 = nullptr, *pHinit = nullptr, *pHlast = nullptr;
    cudaGetSymbolAddress((void**)&pG, g_G);
    cudaGetSymbolAddress((void**)&pSeq, g_seq);
    cudaGetSymbolAddress((void**)&pF1, g_f1);
    cudaGetSymbolAddress((void**)&pHinit, g_hinit);
    cudaGetSymbolAddress((void**)&pHlast, g_hlast);

    int dev = 0, nsm = 148;
    cudaGetDevice(&dev);
    cudaDeviceGetAttribute(&nsm, cudaDevAttrMultiProcessorCount, dev);
    if (nsm < 128) nsm = 128;

    cudaFuncSetAttribute(enc_scan<1, 0, 0>, cudaFuncAttributeMaxDynamicSharedMemorySize, ENC_SMEM);
    cudaFuncSetAttribute(enc_scan<0, 1, 1>, cudaFuncAttributeMaxDynamicSharedMemorySize, ENC_SMEM);

    init_kernel<<<1, 512>>>();
    gemm_nt<ESZ><<<dim3(64, 32), 256>>>(emb, x, eWih0, eb0, pG);
    enc_scan<1, 0, 0><<<128, 256, ENC_SMEM>>>(eWhh0, pG, pSeq);
    gemm_nt<HSZ><<<dim3(64, 32), 256>>>(pSeq, nullptr, eWih1, eb1, pG);
    enc_scan<0, 1, 1><<<128, 256, ENC_SMEM>>>(eWhh1, pG, nullptr);
    fc_relu<<<1024, 256>>>(fc1w, fc1b, pHlast, pF1);
    fc_relu<<<1024, 256>>>(fc2w, fc2b, pF1, pHinit);
    decoder_kernel<<<nsm, DECT>>>(dWih0, dWhh0, db0, dWih1, dWhh1, db1, outw, outb, y, out);
    logsoftmax_kernel<<<TYN, 256>>>(out);
}

// round 8
// speedup vs baseline: 5.0308x; 3.1854x over previous
#include <cuda_runtime.h>
#include <math.h>

// ---------------- problem constants ----------------
#define VSZ   32000
#define ESZ   512
#define HSZ   1024
#define TXN   2048
#define TYN   512
#define G4    4096

// ---------------- device scratch ----------------
__device__ float g_G[(size_t)TXN * G4];
__device__ float g_seq[(size_t)TXN * HSZ];
__device__ float g_h[2][HSZ];
__device__ float g_hlast[HSZ];
__device__ float g_f1[HSZ];
__device__ float g_hinit[HSZ];
__device__ float g_d0[2][HSZ];
__device__ float g_d1[2][HSZ];
__device__ unsigned long long g_amax[TYN - 1];
__device__ unsigned int g_bars[4];

// ---------------- helpers ----------------
__device__ __forceinline__ float wredsum(float v) {
#pragma unroll
    for (int o = 16; o; o >>= 1) v += __shfl_xor_sync(0xffffffffu, v, o);
    return v;
}
__device__ __forceinline__ double wredsum_d(double v) {
#pragma unroll
    for (int o = 16; o; o >>= 1) v += __shfl_xor_sync(0xffffffffu, v, o);
    return v;
}

// fp32 gate eval on lanes 0..3 (accurate expf/tanhf; NOT fast-math intrinsics).
__device__ __forceinline__ void gates4_f(float a0, float a1, float a2, float a3,
                                         float addv, int lane,
                                         float& i_, float& f_, float& g_, float& o_) {
    float asel = (lane == 0) ? a0 : (lane == 1) ? a1 : (lane == 2) ? a2 : a3;
    float gv = 0.0f;
    if (lane < 4) {
        float x = asel + addv;
        gv = (lane == 2) ? tanhf(x) : 1.0f / (1.0f + expf(-x));
    }
    i_ = __shfl_sync(0xffffffffu, gv, 0);
    f_ = __shfl_sync(0xffffffffu, gv, 1);
    g_ = __shfl_sync(0xffffffffu, gv, 2);
    o_ = __shfl_sync(0xffffffffu, gv, 3);
}

// Software grid barrier (all blocks co-resident).
__device__ __forceinline__ void gbar(unsigned int* cnt, unsigned int& epoch) {
    epoch += gridDim.x;
    __threadfence();
    __syncthreads();
    if (threadIdx.x == 0) {
        atomicAdd(cnt, 1);
        while (*(volatile unsigned int*)cnt < epoch) { }
    }
    __syncthreads();
}

// ---------------- init ----------------
__global__ void init_kernel() {
    int i = threadIdx.x;
    if (i < 4) g_bars[i] = 0u;
    for (int j = i; j < TYN - 1; j += blockDim.x) g_amax[j] = 0ull;
}

// ---------------- tiled GEMM (fp32) ----------------
template <int KDIM>
__global__ void gemm_nt(const float* __restrict__ A, const int* __restrict__ ridx,
                        const float* __restrict__ B, const float* __restrict__ bias,
                        float* __restrict__ C) {
    __shared__ float As[64][17];
    __shared__ float Bs[64][17];
    int tid = threadIdx.x;
    int m0 = blockIdx.y * 64, n0 = blockIdx.x * 64;
    int tx = tid & 15, ty = tid >> 4;
    int lrow = tid >> 2;
    int lk4 = (tid & 3) * 4;
    const float* arow = A + (size_t)(ridx ? ridx[m0 + lrow] : (m0 + lrow)) * KDIM;
    const float* brow = B + (size_t)(n0 + lrow) * KDIM;
    float acc[4][4] = {};
    for (int kb = 0; kb < KDIM; kb += 16) {
        float4 av = *(const float4*)(arow + kb + lk4);
        float4 bv = *(const float4*)(brow + kb + lk4);
        __syncthreads();
        As[lrow][lk4 + 0] = av.x; As[lrow][lk4 + 1] = av.y;
        As[lrow][lk4 + 2] = av.z; As[lrow][lk4 + 3] = av.w;
        Bs[lrow][lk4 + 0] = bv.x; Bs[lrow][lk4 + 1] = bv.y;
        Bs[lrow][lk4 + 2] = bv.z; Bs[lrow][lk4 + 3] = bv.w;
        __syncthreads();
#pragma unroll
        for (int kk = 0; kk < 16; kk++) {
            float a[4], b[4];
#pragma unroll
            for (int i = 0; i < 4; i++) a[i] = As[ty * 4 + i][kk];
#pragma unroll
            for (int j = 0; j < 4; j++) b[j] = Bs[tx * 4 + j][kk];
#pragma unroll
            for (int i = 0; i < 4; i++)
#pragma unroll
                for (int j = 0; j < 4; j++) acc[i][j] += a[i] * b[j];
        }
    }
#pragma unroll
    for (int i = 0; i < 4; i++)
#pragma unroll
        for (int j = 0; j < 4; j++)
            C[(size_t)(m0 + ty * 4 + i) * G4 + n0 + tx * 4 + j] =
                acc[i][j] + __ldg(bias + n0 + tx * 4 + j);
}

// ---------------- persistent encoder LSTM scan (Whh in SMEM, fp32) ----------------
#define ENC_SMEM ((8 * 4 * 1024 + 1024) * 4)
template <int WRITE_SEQ, int WRITE_LAST, int BARIDX>
__global__ void __launch_bounds__(256, 1)
enc_scan(const float* __restrict__ Whh, const float* __restrict__ G,
         float* __restrict__ seq) {
    extern __shared__ float sm[];
    float* sW = sm;
    float* sh = sm + 8 * 4 * 1024;
    int tid = threadIdx.x, wid = tid >> 5, lane = tid & 31;
    int unit = blockIdx.x * 8 + wid;
    float* wdst = sW + wid * 4096;
#pragma unroll
    for (int r = 0; r < 4; r++) {
        const float* src = Whh + (size_t)(unit + r * 1024) * 1024;
#pragma unroll
        for (int e = lane * 4; e < 1024; e += 128)
            *(float4*)(wdst + r * 1024 + e) = __ldg((const float4*)(src + e));
    }
    if (blockIdx.x == 0)
        for (int i = tid; i < HSZ; i += blockDim.x) g_h[0][i] = 0.0f;
    unsigned int epoch = 0;
    unsigned int* bar = &g_bars[BARIDX];
    gbar(bar, epoch);
    float c = 0.0f;
    int cur = 0;
    for (int t = 0; t < TXN; t++) {
        *(float4*)(sh + tid * 4) = __ldcg((const float4*)(&g_h[cur][tid * 4]));
        __syncthreads();
        float a0 = 0, a1 = 0, a2 = 0, a3 = 0;
#pragma unroll
        for (int k = 0; k < 8; k++) {
            int j = (k * 32 + lane) << 2;
            float4 h4 = *(float4*)(sh + j);
            float4 w0 = *(float4*)(wdst + j);
            float4 w1 = *(float4*)(wdst + 1024 + j);
            float4 w2 = *(float4*)(wdst + 2048 + j);
            float4 w3 = *(float4*)(wdst + 3072 + j);
            a0 += w0.x * h4.x + w0.y * h4.y + w0.z * h4.z + w0.w * h4.w;
            a1 += w1.x * h4.x + w1.y * h4.y + w1.z * h4.z + w1.w * h4.w;
            a2 += w2.x * h4.x + w2.y * h4.y + w2.z * h4.z + w2.w * h4.w;
            a3 += w3.x * h4.x + w3.y * h4.y + w3.z * h4.z + w3.w * h4.w;
        }
        a0 = wredsum(a0); a1 = wredsum(a1); a2 = wredsum(a2); a3 = wredsum(a3);
        const float* gt = G + (size_t)t * G4;
        float addv = 0.0f;
        if (lane < 4) addv = __ldg(gt + unit + lane * 1024);
        float i_, f_, gg, o_;
        gates4_f(a0, a1, a2, a3, addv, lane, i_, f_, gg, o_);
        if (lane == 0) {
            c = f_ * c + i_ * gg;
            float h = o_ * tanhf(c);
            g_h[cur ^ 1][unit] = h;
            if (WRITE_SEQ) seq[(size_t)t * HSZ + unit] = h;
            if (WRITE_LAST && t == TXN - 1) g_hlast[unit] = h;
        }
        gbar(bar, epoch);
        cur ^= 1;
    }
}

// ---------------- fc + relu (fp64 accumulate — off hot path) ----------------
__global__ void fc_relu(const float* __restrict__ W, const float* __restrict__ b,
                        const float* __restrict__ in, float* __restrict__ out) {
    __shared__ double red[8];
    int r = blockIdx.x, tid = threadIdx.x, wid = tid >> 5, lane = tid & 31;
    const float* wr = W + (size_t)r * 1024;
    float4 w = __ldg((const float4*)(wr + tid * 4));
    float4 v = __ldg((const float4*)(in + tid * 4));
    double acc = (double)(w.x * v.x) + (double)(w.y * v.y) +
                 (double)(w.z * v.z) + (double)(w.w * v.w);
    acc = wredsum_d(acc);
    if (lane == 0) red[wid] = acc;
    __syncthreads();
    if (tid == 0) {
        double s = 0;
#pragma unroll
        for (int i = 0; i < 8; i++) s += red[i];
        double val = s + (double)__ldg(b + r);
        out[r] = (float)(val > 0.0 ? val : 0.0);
    }
}

// ---------------- persistent greedy decoder (fp32 hot path) ----------------
#define DECT 512
__global__ void __launch_bounds__(DECT, 1)
decoder_kernel(
    const float* __restrict__ dWih0, const float* __restrict__ dWhh0, const float* __restrict__ db0,
    const float* __restrict__ dWih1, const float* __restrict__ dWhh1, const float* __restrict__ db1,
    const float* __restrict__ outw, const float* __restrict__ outb,
    const int* __restrict__ y, float* __restrict__ out) {
    __shared__ float sh0[HSZ];
    __shared__ float sh1[HSZ];
    __shared__ unsigned long long skeys[16];
    int tid = threadIdx.x, wid = tid >> 5, lane = tid & 31;
    int unit = blockIdx.x * 16 + wid;
    unsigned int epoch = 0;
    unsigned int* bar = &g_bars[2];
    if (blockIdx.x == 0)
        for (int i = tid; i < HSZ; i += blockDim.x) {
            float v = g_hinit[i];
            g_d0[0][i] = v; g_d1[0][i] = v;
        }
    float c0 = 0.0f, c1 = 0.0f;
    if (unit < HSZ) { c0 = __ldg(&g_hinit[unit]); c1 = c0; }
    gbar(bar, epoch);
    int cur = 0;
    float xt0 = (float)__ldg(&y[0]);
    int gw = blockIdx.x * 16 + wid, nw = gridDim.x * 16;

    for (int t = 0; t < TYN - 1; t++) {
        float xt;
        if (t == 0) xt = xt0;
        else {
            unsigned long long key = __ldcg(&g_amax[t - 1]);
            xt = (float)(0xFFFFFFFFu - (unsigned int)(key & 0xFFFFFFFFull));
        }
        // ---- layer 0 ----
        if (tid < 256)
            *(float4*)(sh0 + tid * 4) = __ldcg((const float4*)(&g_d0[cur][tid * 4]));
        __syncthreads();
        if (unit < HSZ) {
            float a0 = 0, a1 = 0, a2 = 0, a3 = 0;
            const float* b = dWhh0 + (size_t)unit * 1024;
#pragma unroll
            for (int k = 0; k < 8; k++) {
                int j = (k * 32 + lane) << 2;
                float4 h4 = *(float4*)(sh0 + j);
                float4 w;
                w = __ldg((const float4*)(b + j));
                a0 += w.x * h4.x + w.y * h4.y + w.z * h4.z + w.w * h4.w;
                w = __ldg((const float4*)(b + (1 << 20) + j));
                a1 += w.x * h4.x + w.y * h4.y + w.z * h4.z + w.w * h4.w;
                w = __ldg((const float4*)(b + (2 << 20) + j));
                a2 += w.x * h4.x + w.y * h4.y + w.z * h4.z + w.w * h4.w;
                w = __ldg((const float4*)(b + (3 << 20) + j));
                a3 += w.x * h4.x + w.y * h4.y + w.z * h4.z + w.w * h4.w;
            }
            a0 = wredsum(a0); a1 = wredsum(a1); a2 = wredsum(a2); a3 = wredsum(a3);
            float addv = 0.0f;
            if (lane < 4)
                addv = __ldg(dWih0 + unit + lane * 1024) * xt + __ldg(db0 + unit + lane * 1024);
            float i_, f_, gg, o_;
            gates4_f(a0, a1, a2, a3, addv, lane, i_, f_, gg, o_);
            if (lane == 0) {
                c0 = f_ * c0 + i_ * gg;
                g_d0[cur ^ 1][unit] = o_ * tanhf(c0);
            }
        }
        gbar(bar, epoch);
        // ---- layer 1 ----
        if (tid < 256) {
            *(float4*)(sh0 + tid * 4) = __ldcg((const float4*)(&g_d0[cur ^ 1][tid * 4]));
            *(float4*)(sh1 + tid * 4) = __ldcg((const float4*)(&g_d1[cur][tid * 4]));
        }
        __syncthreads();
        if (unit < HSZ) {
            float a0 = 0, a1 = 0, a2 = 0, a3 = 0;
            const float* bi = dWih1 + (size_t)unit * 1024;
            const float* bh = dWhh1 + (size_t)unit * 1024;
#pragma unroll
            for (int k = 0; k < 8; k++) {
                int j = (k * 32 + lane) << 2;
                float4 ha = *(float4*)(sh0 + j);
                float4 hb = *(float4*)(sh1 + j);
                float4 w;
                w = __ldg((const float4*)(bi + j));
                a0 += w.x * ha.x + w.y * ha.y + w.z * ha.z + w.w * ha.w;
                w = __ldg((const float4*)(bh + j));
                a0 += w.x * hb.x + w.y * hb.y + w.z * hb.z + w.w * hb.w;
                w = __ldg((const float4*)(bi + (1 << 20) + j));
                a1 += w.x * ha.x + w.y * ha.y + w.z * ha.z + w.w * ha.w;
                w = __ldg((const float4*)(bh + (1 << 20) + j));
                a1 += w.x * hb.x + w.y * hb.y + w.z * hb.z + w.w * hb.w;
                w = __ldg((const float4*)(bi + (2 << 20) + j));
                a2 += w.x * ha.x + w.y * ha.y + w.z * ha.z + w.w * ha.w;
                w = __ldg((const float4*)(bh + (2 << 20) + j));
                a2 += w.x * hb.x + w.y * hb.y + w.z * hb.z + w.w * hb.w;
                w = __ldg((const float4*)(bi + (3 << 20) + j));
                a3 += w.x * ha.x + w.y * ha.y + w.z * ha.z + w.w * ha.w;
                w = __ldg((const float4*)(bh + (3 << 20) + j));
                a3 += w.x * hb.x + w.y * hb.y + w.z * hb.z + w.w * hb.w;
            }
            a0 = wredsum(a0); a1 = wredsum(a1); a2 = wredsum(a2); a3 = wredsum(a3);
            float addv = 0.0f;
            if (lane < 4) addv = __ldg(db1 + unit + lane * 1024);
            float i_, f_, gg, o_;
            gates4_f(a0, a1, a2, a3, addv, lane, i_, f_, gg, o_);
            if (lane == 0) {
                c1 = f_ * c1 + i_ * gg;
                g_d1[cur ^ 1][unit] = o_ * tanhf(c1);
            }
        }
        gbar(bar, epoch);
        // ---- projection + argmax (fp32, ILP-2 over rows) ----
        if (tid < 256)
            *(float4*)(sh1 + tid * 4) = __ldcg((const float4*)(&g_d1[cur ^ 1][tid * 4]));
        __syncthreads();
        float bestv = -INFINITY; int besti = 0;
        float* orow = out + (size_t)(t + 1) * VSZ;
        int r = gw;
        for (; r + nw < VSZ; r += 2 * nw) {
            int r2 = r + nw;
            const float* wr0 = outw + (size_t)r * 1024;
            const float* wr1 = outw + (size_t)r2 * 1024;
            float pA0 = 0, pA1 = 0, pB0 = 0, pB1 = 0;
#pragma unroll
            for (int k = 0; k < 8; k += 2) {
                int j0 = (k * 32 + lane) << 2;
                int j1 = ((k + 1) * 32 + lane) << 2;
                float4 wa0 = __ldcs((const float4*)(wr0 + j0));
                float4 wa1 = __ldcs((const float4*)(wr0 + j1));
                float4 wb0 = __ldcs((const float4*)(wr1 + j0));
                float4 wb1 = __ldcs((const float4*)(wr1 + j1));
                float4 h40 = *(float4*)(sh1 + j0);
                float4 h41 = *(float4*)(sh1 + j1);
                pA0 += wa0.x * h40.x + wa0.y * h40.y + wa0.z * h40.z + wa0.w * h40.w;
                pA1 += wa1.x * h41.x + wa1.y * h41.y + wa1.z * h41.z + wa1.w * h41.w;
                pB0 += wb0.x * h40.x + wb0.y * h40.y + wb0.z * h40.z + wb0.w * h40.w;
                pB1 += wb1.x * h41.x + wb1.y * h41.y + wb1.z * h41.z + wb1.w * h41.w;
            }
            float accA = wredsum(pA0 + pA1);
            float accB = wredsum(pB0 + pB1);
            if (lane == 0) {
                float lgA = accA + __ldg(outb + r);
                float lgB = accB + __ldg(outb + r2);
                orow[r] = lgA;
                orow[r2] = lgB;
                if (lgA > bestv) { bestv = lgA; besti = r; }
                if (lgB > bestv) { bestv = lgB; besti = r2; }
            }
        }
        if (r < VSZ) {
            const float* wr0 = outw + (size_t)r * 1024;
            float p0 = 0, p1 = 0;
#pragma unroll
            for (int k = 0; k < 8; k += 2) {
                int j0 = (k * 32 + lane) << 2;
                int j1 = ((k + 1) * 32 + lane) << 2;
                float4 wa0 = __ldcs((const float4*)(wr0 + j0));
                float4 wa1 = __ldcs((const float4*)(wr0 + j1));
                float4 h40 = *(float4*)(sh1 + j0);
                float4 h41 = *(float4*)(sh1 + j1);
                p0 += wa0.x * h40.x + wa0.y * h40.y + wa0.z * h40.z + wa0.w * h40.w;
                p1 += wa1.x * h41.x + wa1.y * h41.y + wa1.z * h41.z + wa1.w * h41.w;
            }
            float acc = wredsum(p0 + p1);
            if (lane == 0) {
                float lg = acc + __ldg(outb + r);
                orow[r] = lg;
                if (lg > bestv) { bestv = lg; besti = r; }
            }
        }
        if (lane == 0) {
            unsigned int u = __float_as_uint(bestv);
            u = (u & 0x80000000u) ? ~u : (u | 0x80000000u);
            skeys[wid] = ((unsigned long long)u << 32) |
                         (unsigned long long)(0xFFFFFFFFu - (unsigned int)besti);
        }
        __syncthreads();
        if (tid == 0) {
            unsigned long long k0 = skeys[0];
#pragma unroll
            for (int w = 1; w < 16; w++) if (skeys[w] > k0) k0 = skeys[w];
            atomicMax(&g_amax[t], k0);
        }
        gbar(bar, epoch);
        cur ^= 1;
    }
}

// ---------------- final log_softmax over rows (in place) ----------------
__global__ void logsoftmax_kernel(float* __restrict__ out) {
    int row = blockIdx.x, tid = threadIdx.x, wid = tid >> 5, lane = tid & 31;
    float* p = out + (size_t)row * VSZ;
    if (row == 0) {
        float v = -(float)log((double)VSZ);
        for (int i = tid; i < VSZ; i += blockDim.x) p[i] = v;
        return;
    }
    __shared__ double redd[8];
    __shared__ float redf[8];
    __shared__ float bcf;
    __shared__ double bcd;
    float m = -INFINITY;
    for (int i = tid; i < VSZ; i += blockDim.x) m = fmaxf(m, p[i]);
#pragma unroll
    for (int o = 16; o; o >>= 1) m = fmaxf(m, __shfl_xor_sync(0xffffffffu, m, o));
    if (lane == 0) redf[wid] = m;
    __syncthreads();
    if (tid == 0) {
        float mm = redf[0];
#pragma unroll
        for (int i = 1; i < 8; i++) mm = fmaxf(mm, redf[i]);
        bcf = mm;
    }
    __syncthreads();
    m = bcf;
    double s = 0;
    for (int i = tid; i < VSZ; i += blockDim.x) s += (double)expf(p[i] - m);
    s = wredsum_d(s);
    if (lane == 0) redd[wid] = s;
    __syncthreads();
    if (tid == 0) {
        double ss = 0;
#pragma unroll
        for (int i = 0; i < 8; i++) ss += redd[i];
        bcd = (double)m + log(ss);
    }
    __syncthreads();
    double lse = bcd;
    for (int i = tid; i < VSZ; i += blockDim.x) p[i] = (float)((double)p[i] - lse);
}

// ---------------- launch ----------------
extern "C" void kernel_launch(void* const* d_in, const int* in_sizes, int n_in,
                              void* d_out, int out_size) {
    const int*   x     = (const int*)d_in[0];
    const int*   y     = (const int*)d_in[1];
    const float* emb   = (const float*)d_in[2];
    const float* eWih0 = (const float*)d_in[3];
    const float* eWhh0 = (const float*)d_in[4];
    const float* eb0   = (const float*)d_in[5];
    const float* eWih1 = (const float*)d_in[6];
    const float* eWhh1 = (const float*)d_in[7];
    const float* eb1   = (const float*)d_in[8];
    const float* fc1w  = (const float*)d_in[9];
    const float* fc1b  = (const float*)d_in[10];
    const float* fc2w  = (const float*)d_in[11];
    const float* fc2b  = (const float*)d_in[12];
    const float* dWih0 = (const float*)d_in[13];
    const float* dWhh0 = (const float*)d_in[14];
    const float* db0   = (const float*)d_in[15];
    const float* dWih1 = (const float*)d_in[16];
    const float* dWhh1 = (const float*)d_in[17];
    const float* db1   = (const float*)d_in[18];
    const float* outw  = (const float*)d_in[19];
    const float* outb  = (const float*)d_in[20];
    float* out = (float*)d_out;

    float *pG = nullptr, *pSeq = nullptr, *pF1 = nullptr, *pHinit = nullptr, *pHlast = nullptr;
    cudaGetSymbolAddress((void**)&pG, g_G);
    cudaGetSymbolAddress((void**)&pSeq, g_seq);
    cudaGetSymbolAddress((void**)&pF1, g_f1);
    cudaGetSymbolAddress((void**)&pHinit, g_hinit);
    cudaGetSymbolAddress((void**)&pHlast, g_hlast);

    int dev = 0, nsm = 148;
    cudaGetDevice(&dev);
    cudaDeviceGetAttribute(&nsm, cudaDevAttrMultiProcessorCount, dev);
    if (nsm < 128) nsm = 128;

    cudaFuncSetAttribute(enc_scan<1, 0, 0>, cudaFuncAttributeMaxDynamicSharedMemorySize, ENC_SMEM);
    cudaFuncSetAttribute(enc_scan<0, 1, 1>, cudaFuncAttributeMaxDynamicSharedMemorySize, ENC_SMEM);

    init_kernel<<<1, 512>>>();
    gemm_nt<ESZ><<<dim3(64, 32), 256>>>(emb, x, eWih0, eb0, pG);
    enc_scan<1, 0, 0><<<128, 256, ENC_SMEM>>>(eWhh0, pG, pSeq);
    gemm_nt<HSZ><<<dim3(64, 32), 256>>>(pSeq, nullptr, eWih1, eb1, pG);
    enc_scan<0, 1, 1><<<128, 256, ENC_SMEM>>>(eWhh1, pG, nullptr);
    fc_relu<<<1024, 256>>>(fc1w, fc1b, pHlast, pF1);
    fc_relu<<<1024, 256>>>(fc2w, fc2b, pF1, pHinit);
    decoder_kernel<<<nsm, DECT>>>(dWih0, dWhh0, db0, dWih1, dWhh1, db1, outw, outb, y, out);
    logsoftmax_kernel<<<TYN, 256>>>(out);
}

// round 9
// speedup vs baseline: 5.2483x; 1.0432x over previous
#include <cuda_runtime.h>
#include <cuda_bf16.h>
#include <math.h>

// ---------------- problem constants ----------------
#define VSZ   32000
#define ESZ   512
#define HSZ   1024
#define TXN   2048
#define TYN   512
#define G4    4096
#define MARGIN 0.03f

// ---------------- device scratch ----------------
__device__ float g_G[(size_t)TXN * G4];
__device__ float g_seq[(size_t)TXN * HSZ];
__device__ unsigned g_owbf[(size_t)VSZ * HSZ / 2];   // bf16 out_w (65.5MB), 2 per uint
__device__ float g_h[2][HSZ];
__device__ float g_hlast[HSZ];
__device__ float g_f1[HSZ];
__device__ float g_hinit[HSZ];
__device__ float g_d0[2][HSZ];
__device__ float g_d1[2][HSZ];
__device__ unsigned long long g_amax[TYN - 1];    // bf16-phase keys
__device__ unsigned long long g_amax2[TYN - 1];   // fp32 rescue keys (final)
__device__ unsigned int g_bars[4];

// ---------------- helpers ----------------
__device__ __forceinline__ float wredsum(float v) {
#pragma unroll
    for (int o = 16; o; o >>= 1) v += __shfl_xor_sync(0xffffffffu, v, o);
    return v;
}
__device__ __forceinline__ double wredsum_d(double v) {
#pragma unroll
    for (int o = 16; o; o >>= 1) v += __shfl_xor_sync(0xffffffffu, v, o);
    return v;
}
__device__ __forceinline__ float bflo(unsigned u) { return __uint_as_float(u << 16); }
__device__ __forceinline__ float bfhi(unsigned u) { return __uint_as_float(u & 0xFFFF0000u); }

__device__ __forceinline__ unsigned long long mkkey(float v, int idx) {
    unsigned u = __float_as_uint(v);
    u = (u & 0x80000000u) ? ~u : (u | 0x80000000u);
    return ((unsigned long long)u << 32) |
           (unsigned long long)(0xFFFFFFFFu - (unsigned)idx);
}
__device__ __forceinline__ float keyval(unsigned long long k) {
    unsigned enc = (unsigned)(k >> 32);
    unsigned fu = (enc & 0x80000000u) ? (enc & 0x7FFFFFFFu) : ~enc;
    return __uint_as_float(fu);
}

// fp32 gate eval on lanes 0..3 (accurate expf/tanhf).
__device__ __forceinline__ void gates4_f(float a0, float a1, float a2, float a3,
                                         float addv, int lane,
                                         float& i_, float& f_, float& g_, float& o_) {
    float asel = (lane == 0) ? a0 : (lane == 1) ? a1 : (lane == 2) ? a2 : a3;
    float gv = 0.0f;
    if (lane < 4) {
        float x = asel + addv;
        gv = (lane == 2) ? tanhf(x) : 1.0f / (1.0f + expf(-x));
    }
    i_ = __shfl_sync(0xffffffffu, gv, 0);
    f_ = __shfl_sync(0xffffffffu, gv, 1);
    g_ = __shfl_sync(0xffffffffu, gv, 2);
    o_ = __shfl_sync(0xffffffffu, gv, 3);
}

// Software grid barrier (all blocks co-resident).
__device__ __forceinline__ void gbar(unsigned int* cnt, unsigned int& epoch) {
    epoch += gridDim.x;
    __threadfence();
    __syncthreads();
    if (threadIdx.x == 0) {
        atomicAdd(cnt, 1);
        while (*(volatile unsigned int*)cnt < epoch) { }
    }
    __syncthreads();
}

// ---------------- init ----------------
__global__ void init_kernel() {
    int i = threadIdx.x;
    if (i < 4) g_bars[i] = 0u;
    for (int j = i; j < TYN - 1; j += blockDim.x) { g_amax[j] = 0ull; g_amax2[j] = 0ull; }
}

// ---------------- out_w fp32 -> bf16 conversion (one-time, ~30us) ----------------
__global__ void conv_bf16(const float* __restrict__ w) {
    size_t i = (size_t)blockIdx.x * blockDim.x + threadIdx.x;   // one float4 per thread
    float4 v = *(const float4*)(w + i * 4);
    unsigned b0 = (unsigned)__bfloat16_as_ushort(__float2bfloat16_rn(v.x)) |
                  ((unsigned)__bfloat16_as_ushort(__float2bfloat16_rn(v.y)) << 16);
    unsigned b1 = (unsigned)__bfloat16_as_ushort(__float2bfloat16_rn(v.z)) |
                  ((unsigned)__bfloat16_as_ushort(__float2bfloat16_rn(v.w)) << 16);
    g_owbf[i * 2] = b0;
    g_owbf[i * 2 + 1] = b1;
}

// ---------------- tiled GEMM (fp32) ----------------
template <int KDIM>
__global__ void gemm_nt(const float* __restrict__ A, const int* __restrict__ ridx,
                        const float* __restrict__ B, const float* __restrict__ bias,
                        float* __restrict__ C) {
    __shared__ float As[64][17];
    __shared__ float Bs[64][17];
    int tid = threadIdx.x;
    int m0 = blockIdx.y * 64, n0 = blockIdx.x * 64;
    int tx = tid & 15, ty = tid >> 4;
    int lrow = tid >> 2;
    int lk4 = (tid & 3) * 4;
    const float* arow = A + (size_t)(ridx ? ridx[m0 + lrow] : (m0 + lrow)) * KDIM;
    const float* brow = B + (size_t)(n0 + lrow) * KDIM;
    float acc[4][4] = {};
    for (int kb = 0; kb < KDIM; kb += 16) {
        float4 av = *(const float4*)(arow + kb + lk4);
        float4 bv = *(const float4*)(brow + kb + lk4);
        __syncthreads();
        As[lrow][lk4 + 0] = av.x; As[lrow][lk4 + 1] = av.y;
        As[lrow][lk4 + 2] = av.z; As[lrow][lk4 + 3] = av.w;
        Bs[lrow][lk4 + 0] = bv.x; Bs[lrow][lk4 + 1] = bv.y;
        Bs[lrow][lk4 + 2] = bv.z; Bs[lrow][lk4 + 3] = bv.w;
        __syncthreads();
#pragma unroll
        for (int kk = 0; kk < 16; kk++) {
            float a[4], b[4];
#pragma unroll
            for (int i = 0; i < 4; i++) a[i] = As[ty * 4 + i][kk];
#pragma unroll
            for (int j = 0; j < 4; j++) b[j] = Bs[tx * 4 + j][kk];
#pragma unroll
            for (int i = 0; i < 4; i++)
#pragma unroll
                for (int j = 0; j < 4; j++) acc[i][j] += a[i] * b[j];
        }
    }
#pragma unroll
    for (int i = 0; i < 4; i++)
#pragma unroll
        for (int j = 0; j < 4; j++)
            C[(size_t)(m0 + ty * 4 + i) * G4 + n0 + tx * 4 + j] =
                acc[i][j] + __ldg(bias + n0 + tx * 4 + j);
}

// ---------------- persistent encoder LSTM scan (Whh in SMEM, fp32) ----------------
#define ENC_SMEM ((8 * 4 * 1024 + 1024) * 4)
template <int WRITE_SEQ, int WRITE_LAST, int BARIDX>
__global__ void __launch_bounds__(256, 1)
enc_scan(const float* __restrict__ Whh, const float* __restrict__ G,
         float* __restrict__ seq) {
    extern __shared__ float sm[];
    float* sW = sm;
    float* sh = sm + 8 * 4 * 1024;
    int tid = threadIdx.x, wid = tid >> 5, lane = tid & 31;
    int unit = blockIdx.x * 8 + wid;
    float* wdst = sW + wid * 4096;
#pragma unroll
    for (int r = 0; r < 4; r++) {
        const float* src = Whh + (size_t)(unit + r * 1024) * 1024;
#pragma unroll
        for (int e = lane * 4; e < 1024; e += 128)
            *(float4*)(wdst + r * 1024 + e) = __ldg((const float4*)(src + e));
    }
    if (blockIdx.x == 0)
        for (int i = tid; i < HSZ; i += blockDim.x) g_h[0][i] = 0.0f;
    unsigned int epoch = 0;
    unsigned int* bar = &g_bars[BARIDX];
    gbar(bar, epoch);
    float c = 0.0f;
    int cur = 0;
    for (int t = 0; t < TXN; t++) {
        // hoist G load (DRAM-cold) ahead of matvec to hide latency
        const float* gt = G + (size_t)t * G4;
        float addv = 0.0f;
        if (lane < 4) addv = __ldg(gt + unit + lane * 1024);
        *(float4*)(sh + tid * 4) = __ldcg((const float4*)(&g_h[cur][tid * 4]));
        __syncthreads();
        float a0 = 0, a1 = 0, a2 = 0, a3 = 0;
#pragma unroll
        for (int k = 0; k < 8; k++) {
            int j = (k * 32 + lane) << 2;
            float4 h4 = *(float4*)(sh + j);
            float4 w0 = *(float4*)(wdst + j);
            float4 w1 = *(float4*)(wdst + 1024 + j);
            float4 w2 = *(float4*)(wdst + 2048 + j);
            float4 w3 = *(float4*)(wdst + 3072 + j);
            a0 += w0.x * h4.x + w0.y * h4.y + w0.z * h4.z + w0.w * h4.w;
            a1 += w1.x * h4.x + w1.y * h4.y + w1.z * h4.z + w1.w * h4.w;
            a2 += w2.x * h4.x + w2.y * h4.y + w2.z * h4.z + w2.w * h4.w;
            a3 += w3.x * h4.x + w3.y * h4.y + w3.z * h4.z + w3.w * h4.w;
        }
        a0 = wredsum(a0); a1 = wredsum(a1); a2 = wredsum(a2); a3 = wredsum(a3);
        float i_, f_, gg, o_;
        gates4_f(a0, a1, a2, a3, addv, lane, i_, f_, gg, o_);
        if (lane == 0) {
            c = f_ * c + i_ * gg;
            float h = o_ * tanhf(c);
            g_h[cur ^ 1][unit] = h;
            if (WRITE_SEQ) seq[(size_t)t * HSZ + unit] = h;
            if (WRITE_LAST && t == TXN - 1) g_hlast[unit] = h;
        }
        gbar(bar, epoch);
        cur ^= 1;
    }
}

// ---------------- fc + relu (fp64, off hot path) ----------------
__global__ void fc_relu(const float* __restrict__ W, const float* __restrict__ b,
                        const float* __restrict__ in, float* __restrict__ out) {
    __shared__ double red[8];
    int r = blockIdx.x, tid = threadIdx.x, wid = tid >> 5, lane = tid & 31;
    const float* wr = W + (size_t)r * 1024;
    float4 w = __ldg((const float4*)(wr + tid * 4));
    float4 v = __ldg((const float4*)(in + tid * 4));
    double acc = (double)(w.x * v.x) + (double)(w.y * v.y) +
                 (double)(w.z * v.z) + (double)(w.w * v.w);
    acc = wredsum_d(acc);
    if (lane == 0) red[wid] = acc;
    __syncthreads();
    if (tid == 0) {
        double s = 0;
#pragma unroll
        for (int i = 0; i < 8; i++) s += red[i];
        double val = s + (double)__ldg(b + r);
        out[r] = (float)(val > 0.0 ? val : 0.0);
    }
}

// ---------------- persistent greedy decoder ----------------
#define DECT 512
__global__ void __launch_bounds__(DECT, 1)
decoder_kernel(
    const float* __restrict__ dWih0, const float* __restrict__ dWhh0, const float* __restrict__ db0,
    const float* __restrict__ dWih1, const float* __restrict__ dWhh1, const float* __restrict__ db1,
    const float* __restrict__ outw, const float* __restrict__ outb,
    const int* __restrict__ y, float* __restrict__ out) {
    __shared__ float sh0[HSZ];
    __shared__ float sh1[HSZ];
    __shared__ unsigned long long skeys[16];
    int tid = threadIdx.x, wid = tid >> 5, lane = tid & 31;
    int unit = blockIdx.x * 16 + wid;
    unsigned int epoch = 0;
    unsigned int* bar = &g_bars[2];
    if (blockIdx.x == 0)
        for (int i = tid; i < HSZ; i += blockDim.x) {
            float v = g_hinit[i];
            g_d0[0][i] = v; g_d1[0][i] = v;
        }
    float c0 = 0.0f, c1 = 0.0f;
    if (unit < HSZ) { c0 = __ldg(&g_hinit[unit]); c1 = c0; }
    gbar(bar, epoch);
    int cur = 0;
    float xt0 = (float)__ldg(&y[0]);
    int gw = blockIdx.x * 16 + wid, nw = gridDim.x * 16;

    for (int t = 0; t < TYN - 1; t++) {
        float xt;
        if (t == 0) xt = xt0;
        else {
            unsigned long long key = __ldcg(&g_amax2[t - 1]);
            xt = (float)(0xFFFFFFFFu - (unsigned int)(key & 0xFFFFFFFFull));
        }
        // ---- layer 0 ----
        if (tid < 256)
            *(float4*)(sh0 + tid * 4) = __ldcg((const float4*)(&g_d0[cur][tid * 4]));
        __syncthreads();
        if (unit < HSZ) {
            float a0 = 0, a1 = 0, a2 = 0, a3 = 0;
            const float* b = dWhh0 + (size_t)unit * 1024;
#pragma unroll
            for (int k = 0; k < 8; k++) {
                int j = (k * 32 + lane) << 2;
                float4 h4 = *(float4*)(sh0 + j);
                float4 w;
                w = __ldg((const float4*)(b + j));
                a0 += w.x * h4.x + w.y * h4.y + w.z * h4.z + w.w * h4.w;
                w = __ldg((const float4*)(b + (1 << 20) + j));
                a1 += w.x * h4.x + w.y * h4.y + w.z * h4.z + w.w * h4.w;
                w = __ldg((const float4*)(b + (2 << 20) + j));
                a2 += w.x * h4.x + w.y * h4.y + w.z * h4.z + w.w * h4.w;
                w = __ldg((const float4*)(b + (3 << 20) + j));
                a3 += w.x * h4.x + w.y * h4.y + w.z * h4.z + w.w * h4.w;
            }
            a0 = wredsum(a0); a1 = wredsum(a1); a2 = wredsum(a2); a3 = wredsum(a3);
            float addv = 0.0f;
            if (lane < 4)
                addv = __ldg(dWih0 + unit + lane * 1024) * xt + __ldg(db0 + unit + lane * 1024);
            float i_, f_, gg, o_;
            gates4_f(a0, a1, a2, a3, addv, lane, i_, f_, gg, o_);
            if (lane == 0) {
                c0 = f_ * c0 + i_ * gg;
                g_d0[cur ^ 1][unit] = o_ * tanhf(c0);
            }
        }
        gbar(bar, epoch);
        // ---- layer 1 ----
        if (tid < 256) {
            *(float4*)(sh0 + tid * 4) = __ldcg((const float4*)(&g_d0[cur ^ 1][tid * 4]));
            *(float4*)(sh1 + tid * 4) = __ldcg((const float4*)(&g_d1[cur][tid * 4]));
        }
        __syncthreads();
        if (unit < HSZ) {
            float a0 = 0, a1 = 0, a2 = 0, a3 = 0;
            const float* bi = dWih1 + (size_t)unit * 1024;
            const float* bh = dWhh1 + (size_t)unit * 1024;
#pragma unroll
            for (int k = 0; k < 8; k++) {
                int j = (k * 32 + lane) << 2;
                float4 ha = *(float4*)(sh0 + j);
                float4 hb = *(float4*)(sh1 + j);
                float4 w;
                w = __ldg((const float4*)(bi + j));
                a0 += w.x * ha.x + w.y * ha.y + w.z * ha.z + w.w * ha.w;
                w = __ldg((const float4*)(bh + j));
                a0 += w.x * hb.x + w.y * hb.y + w.z * hb.z + w.w * hb.w;
                w = __ldg((const float4*)(bi + (1 << 20) + j));
                a1 += w.x * ha.x + w.y * ha.y + w.z * ha.z + w.w * ha.w;
                w = __ldg((const float4*)(bh + (1 << 20) + j));
                a1 += w.x * hb.x + w.y * hb.y + w.z * hb.z + w.w * hb.w;
                w = __ldg((const float4*)(bi + (2 << 20) + j));
                a2 += w.x * ha.x + w.y * ha.y + w.z * ha.z + w.w * ha.w;
                w = __ldg((const float4*)(bh + (2 << 20) + j));
                a2 += w.x * hb.x + w.y * hb.y + w.z * hb.z + w.w * hb.w;
                w = __ldg((const float4*)(bi + (3 << 20) + j));
                a3 += w.x * ha.x + w.y * ha.y + w.z * ha.z + w.w * ha.w;
                w = __ldg((const float4*)(bh + (3 << 20) + j));
                a3 += w.x * hb.x + w.y * hb.y + w.z * hb.z + w.w * hb.w;
            }
            a0 = wredsum(a0); a1 = wredsum(a1); a2 = wredsum(a2); a3 = wredsum(a3);
            float addv = 0.0f;
            if (lane < 4) addv = __ldg(db1 + unit + lane * 1024);
            float i_, f_, gg, o_;
            gates4_f(a0, a1, a2, a3, addv, lane, i_, f_, gg, o_);
            if (lane == 0) {
                c1 = f_ * c1 + i_ * gg;
                g_d1[cur ^ 1][unit] = o_ * tanhf(c1);
            }
        }
        gbar(bar, epoch);
        // ---- phase A: bf16 projection + bf16 argmax (ILP-2 rows) ----
        if (tid < 256)
            *(float4*)(sh1 + tid * 4) = __ldcg((const float4*)(&g_d1[cur ^ 1][tid * 4]));
        __syncthreads();
        float bestv = -INFINITY; int besti = 0;
        float* orow = out + (size_t)(t + 1) * VSZ;
        int r = gw;
        for (; r + nw < VSZ; r += 2 * nw) {
            int r2 = r + nw;
            const uint4* wr0 = (const uint4*)(g_owbf + (size_t)r * 512);
            const uint4* wr1 = (const uint4*)(g_owbf + (size_t)r2 * 512);
            float pA0 = 0, pA1 = 0, pB0 = 0, pB1 = 0;
#pragma unroll
            for (int k = 0; k < 4; k++) {
                int q = k * 32 + lane;            // uint4 index; covers elems [8q, 8q+8)
                uint4 wa = __ldcs(wr0 + q);
                uint4 wb = __ldcs(wr1 + q);
                float4 h0 = *(float4*)(sh1 + 8 * q);
                float4 h1 = *(float4*)(sh1 + 8 * q + 4);
                pA0 += bflo(wa.x) * h0.x + bfhi(wa.x) * h0.y + bflo(wa.y) * h0.z + bfhi(wa.y) * h0.w;
                pA1 += bflo(wa.z) * h1.x + bfhi(wa.z) * h1.y + bflo(wa.w) * h1.z + bfhi(wa.w) * h1.w;
                pB0 += bflo(wb.x) * h0.x + bfhi(wb.x) * h0.y + bflo(wb.y) * h0.z + bfhi(wb.y) * h0.w;
                pB1 += bflo(wb.z) * h1.x + bfhi(wb.z) * h1.y + bflo(wb.w) * h1.z + bfhi(wb.w) * h1.w;
            }
            float accA = wredsum(pA0 + pA1);
            float accB = wredsum(pB0 + pB1);
            if (lane == 0) {
                float lgA = accA + __ldg(outb + r);
                float lgB = accB + __ldg(outb + r2);
                orow[r] = lgA;
                orow[r2] = lgB;
                if (lgA > bestv) { bestv = lgA; besti = r; }
                if (lgB > bestv) { bestv = lgB; besti = r2; }
            }
        }
        if (r < VSZ) {
            const uint4* wr0 = (const uint4*)(g_owbf + (size_t)r * 512);
            float p0 = 0, p1 = 0;
#pragma unroll
            for (int k = 0; k < 4; k++) {
                int q = k * 32 + lane;
                uint4 wa = __ldcs(wr0 + q);
                float4 h0 = *(float4*)(sh1 + 8 * q);
                float4 h1 = *(float4*)(sh1 + 8 * q + 4);
                p0 += bflo(wa.x) * h0.x + bfhi(wa.x) * h0.y + bflo(wa.y) * h0.z + bfhi(wa.y) * h0.w;
                p1 += bflo(wa.z) * h1.x + bfhi(wa.z) * h1.y + bflo(wa.w) * h1.z + bfhi(wa.w) * h1.w;
            }
            float acc = wredsum(p0 + p1);
            if (lane == 0) {
                float lg = acc + __ldg(outb + r);
                orow[r] = lg;
                if (lg > bestv) { bestv = lg; besti = r; }
            }
        }
        if (lane == 0) skeys[wid] = mkkey(bestv, besti);
        __syncthreads();
        if (tid == 0) {
            unsigned long long k0 = skeys[0];
#pragma unroll
            for (int w = 1; w < 16; w++) if (skeys[w] > k0) k0 = skeys[w];
            atomicMax(&g_amax[t], k0);
        }
        gbar(bar, epoch);
        // ---- phase B: fp32 rescue of rows within MARGIN of bf16-best ----
        {
            float gbest = keyval(__ldcg(&g_amax[t]));
            float thresh = gbest - MARGIN;
            unsigned long long bkey2 = 0ull;
            for (int rr = gw; rr < VSZ; rr += nw) {
                float lg = __shfl_sync(0xffffffffu, (lane == 0) ? orow[rr] : 0.0f, 0);
                if (lg >= thresh) {
                    const float* wrf = outw + (size_t)rr * 1024;
                    float p0 = 0, p1 = 0;
#pragma unroll
                    for (int k = 0; k < 8; k += 2) {
                        int j0 = (k * 32 + lane) << 2;
                        int j1 = ((k + 1) * 32 + lane) << 2;
                        float4 wa0 = __ldg((const float4*)(wrf + j0));
                        float4 wa1 = __ldg((const float4*)(wrf + j1));
                        float4 h40 = *(float4*)(sh1 + j0);
                        float4 h41 = *(float4*)(sh1 + j1);
                        p0 += wa0.x * h40.x + wa0.y * h40.y + wa0.z * h40.z + wa0.w * h40.w;
                        p1 += wa1.x * h41.x + wa1.y * h41.y + wa1.z * h41.z + wa1.w * h41.w;
                    }
                    float accf = wredsum(p0 + p1);
                    if (lane == 0) {
                        float lgf = accf + __ldg(outb + rr);
                        orow[rr] = lgf;                       // exact value for output too
                        unsigned long long kk = mkkey(lgf, rr);
                        if (kk > bkey2) bkey2 = kk;
                    }
                }
            }
            if (lane == 0 && bkey2 != 0ull) atomicMax(&g_amax2[t], bkey2);
        }
        gbar(bar, epoch);
        cur ^= 1;
    }
}

// ---------------- final log_softmax over rows (in place) ----------------
__global__ void logsoftmax_kernel(float* __restrict__ out) {
    int row = blockIdx.x, tid = threadIdx.x, wid = tid >> 5, lane = tid & 31;
    float* p = out + (size_t)row * VSZ;
    if (row == 0) {
        float v = -(float)log((double)VSZ);
        for (int i = tid; i < VSZ; i += blockDim.x) p[i] = v;
        return;
    }
    __shared__ double redd[8];
    __shared__ float redf[8];
    __shared__ float bcf;
    __shared__ double bcd;
    float m = -INFINITY;
    for (int i = tid; i < VSZ; i += blockDim.x) m = fmaxf(m, p[i]);
#pragma unroll
    for (int o = 16; o; o >>= 1) m = fmaxf(m, __shfl_xor_sync(0xffffffffu, m, o));
    if (lane == 0) redf[wid] = m;
    __syncthreads();
    if (tid == 0) {
        float mm = redf[0];
#pragma unroll
        for (int i = 1; i < 8; i++) mm = fmaxf(mm, redf[i]);
        bcf = mm;
    }
    __syncthreads();
    m = bcf;
    double s = 0;
    for (int i = tid; i < VSZ; i += blockDim.x) s += (double)expf(p[i] - m);
    s = wredsum_d(s);
    if (lane == 0) redd[wid] = s;
    __syncthreads();
    if (tid == 0) {
        double ss = 0;
#pragma unroll
        for (int i = 0; i < 8; i++) ss += redd[i];
        bcd = (double)m + log(ss);
    }
    __syncthreads();
    double lse = bcd;
    for (int i = tid; i < VSZ; i += blockDim.x) p[i] = (float)((double)p[i] - lse);
}

// ---------------- launch ----------------
extern "C" void kernel_launch(void* const* d_in, const int* in_sizes, int n_in,
                              void* d_out, int out_size) {
    const int*   x     = (const int*)d_in[0];
    const int*   y     = (const int*)d_in[1];
    const float* emb   = (const float*)d_in[2];
    const float* eWih0 = (const float*)d_in[3];
    const float* eWhh0 = (const float*)d_in[4];
    const float* eb0   = (const float*)d_in[5];
    const float* eWih1 = (const float*)d_in[6];
    const float* eWhh1 = (const float*)d_in[7];
    const float* eb1   = (const float*)d_in[8];
    const float* fc1w  = (const float*)d_in[9];
    const float* fc1b  = (const float*)d_in[10];
    const float* fc2w  = (const float*)d_in[11];
    const float* fc2b  = (const float*)d_in[12];
    const float* dWih0 = (const float*)d_in[13];
    const float* dWhh0 = (const float*)d_in[14];
    const float* db0   = (const float*)d_in[15];
    const float* dWih1 = (const float*)d_in[16];
    const float* dWhh1 = (const float*)d_in[17];
    const float* db1   = (const float*)d_in[18];
    const float* outw  = (const float*)d_in[19];
    const float* outb  = (const float*)d_in[20];
    float* out = (float*)d_out;

    float *pG = nullptr, *pSeq = nullptr, *pF1 = nullptr, *pHinit = nullptr, *pHlast = nullptr;
    cudaGetSymbolAddress((void**)&pG, g_G);
    cudaGetSymbolAddress((void**)&pSeq, g_seq);
    cudaGetSymbolAddress((void**)&pF1, g_f1);
    cudaGetSymbolAddress((void**)&pHinit, g_hinit);
    cudaGetSymbolAddress((void**)&pHlast, g_hlast);

    int dev = 0, nsm = 148;
    cudaGetDevice(&dev);
    cudaDeviceGetAttribute(&nsm, cudaDevAttrMultiProcessorCount, dev);
    if (nsm < 128) nsm = 128;

    cudaFuncSetAttribute(enc_scan<1, 0, 0>, cudaFuncAttributeMaxDynamicSharedMemorySize, ENC_SMEM);
    cudaFuncSetAttribute(enc_scan<0, 1, 1>, cudaFuncAttributeMaxDynamicSharedMemorySize, ENC_SMEM);

    init_kernel<<<1, 512>>>();
    conv_bf16<<<VSZ * (HSZ / 4) / 256, 256>>>(outw);   // 32000*256 threads, 4 elems each
    gemm_nt<ESZ><<<dim3(64, 32), 256>>>(emb, x, eWih0, eb0, pG);
    enc_scan<1, 0, 0><<<128, 256, ENC_SMEM>>>(eWhh0, pG, pSeq);
    gemm_nt<HSZ><<<dim3(64, 32), 256>>>(pSeq, nullptr, eWih1, eb1, pG);
    enc_scan<0, 1, 1><<<128, 256, ENC_SMEM>>>(eWhh1, pG, nullptr);
    fc_relu<<<1024, 256>>>(fc1w, fc1b, pHlast, pF1);
    fc_relu<<<1024, 256>>>(fc2w, fc2b, pF1, pHinit);
    decoder_kernel<<<nsm, DECT>>>(dWih0, dWhh0, db0, dWih1, dWhh1, db1, outw, outb, y, out);
    logsoftmax_kernel<<<TYN, 256>>>(out);
}

// round 10
// speedup vs baseline: 5.9074x; 1.1256x over previous
#include <cuda_runtime.h>
#include <cuda_bf16.h>
#include <math.h>

// ---------------- problem constants ----------------
#define VSZ   32000
#define ESZ   512
#define HSZ   1024
#define TXN   2048
#define TYN   512
#define G4    4096
#define MARGIN 0.03f

// ---------------- device scratch ----------------
__device__ float g_G[(size_t)TXN * G4];
__device__ float g_seq[(size_t)TXN * HSZ];
__device__ unsigned g_owbf[(size_t)VSZ * HSZ / 2];   // bf16 out_w (65.5MB)
__device__ float g_h[2][HSZ];
__device__ float g_hlast[HSZ];
__device__ float g_f1[HSZ];
__device__ float g_hinit[HSZ];
__device__ float g_d0[2][HSZ];
__device__ float g_d1[2][HSZ];
__device__ unsigned long long g_amax[TYN - 1];    // fp32-rescued argmax keys
__device__ unsigned int g_bars[4];

// ---------------- helpers ----------------
__device__ __forceinline__ float wredsum(float v) {
#pragma unroll
    for (int o = 16; o; o >>= 1) v += __shfl_xor_sync(0xffffffffu, v, o);
    return v;
}
__device__ __forceinline__ double wredsum_d(double v) {
#pragma unroll
    for (int o = 16; o; o >>= 1) v += __shfl_xor_sync(0xffffffffu, v, o);
    return v;
}
__device__ __forceinline__ float bflo(unsigned u) { return __uint_as_float(u << 16); }
__device__ __forceinline__ float bfhi(unsigned u) { return __uint_as_float(u & 0xFFFF0000u); }

__device__ __forceinline__ unsigned long long mkkey(float v, int idx) {
    unsigned u = __float_as_uint(v);
    u = (u & 0x80000000u) ? ~u : (u | 0x80000000u);
    return ((unsigned long long)u << 32) |
           (unsigned long long)(0xFFFFFFFFu - (unsigned)idx);
}

// fp32 gate eval on lanes 0..3 (accurate expf/tanhf).
__device__ __forceinline__ void gates4_f(float a0, float a1, float a2, float a3,
                                         float addv, int lane,
                                         float& i_, float& f_, float& g_, float& o_) {
    float asel = (lane == 0) ? a0 : (lane == 1) ? a1 : (lane == 2) ? a2 : a3;
    float gv = 0.0f;
    if (lane < 4) {
        float x = asel + addv;
        gv = (lane == 2) ? tanhf(x) : 1.0f / (1.0f + expf(-x));
    }
    i_ = __shfl_sync(0xffffffffu, gv, 0);
    f_ = __shfl_sync(0xffffffffu, gv, 1);
    g_ = __shfl_sync(0xffffffffu, gv, 2);
    o_ = __shfl_sync(0xffffffffu, gv, 3);
}

// Software grid barrier: release/acquire (NO full GPU membar on critical path).
// tid0 arrives with red.release and spins with ld.acquire; syncthreads
// propagates the ordering block-wide.
__device__ __forceinline__ void gbar(unsigned int* cnt, unsigned int& epoch) {
    epoch += gridDim.x;
    __syncthreads();
    if (threadIdx.x == 0) {
        asm volatile("red.release.gpu.global.add.u32 [%0], %1;"
                     :: "l"(cnt), "r"(1u) : "memory");
        unsigned cur;
        do {
            asm volatile("ld.acquire.gpu.global.u32 %0, [%1];"
                         : "=r"(cur) : "l"(cnt) : "memory");
        } while ((int)(cur - epoch) < 0);
    }
    __syncthreads();
}

// ---------------- init ----------------
__global__ void init_kernel() {
    int i = threadIdx.x;
    if (i < 4) g_bars[i] = 0u;
    for (int j = i; j < TYN - 1; j += blockDim.x) g_amax[j] = 0ull;
}

// ---------------- out_w fp32 -> bf16 (one-time) ----------------
__global__ void conv_bf16(const float* __restrict__ w) {
    size_t i = (size_t)blockIdx.x * blockDim.x + threadIdx.x;
    float4 v = *(const float4*)(w + i * 4);
    unsigned b0 = (unsigned)__bfloat16_as_ushort(__float2bfloat16_rn(v.x)) |
                  ((unsigned)__bfloat16_as_ushort(__float2bfloat16_rn(v.y)) << 16);
    unsigned b1 = (unsigned)__bfloat16_as_ushort(__float2bfloat16_rn(v.z)) |
                  ((unsigned)__bfloat16_as_ushort(__float2bfloat16_rn(v.w)) << 16);
    g_owbf[i * 2] = b0;
    g_owbf[i * 2 + 1] = b1;
}

// ---------------- tiled GEMM (fp32) ----------------
template <int KDIM>
__global__ void gemm_nt(const float* __restrict__ A, const int* __restrict__ ridx,
                        const float* __restrict__ B, const float* __restrict__ bias,
                        float* __restrict__ C) {
    __shared__ float As[64][17];
    __shared__ float Bs[64][17];
    int tid = threadIdx.x;
    int m0 = blockIdx.y * 64, n0 = blockIdx.x * 64;
    int tx = tid & 15, ty = tid >> 4;
    int lrow = tid >> 2;
    int lk4 = (tid & 3) * 4;
    const float* arow = A + (size_t)(ridx ? ridx[m0 + lrow] : (m0 + lrow)) * KDIM;
    const float* brow = B + (size_t)(n0 + lrow) * KDIM;
    float acc[4][4] = {};
    for (int kb = 0; kb < KDIM; kb += 16) {
        float4 av = *(const float4*)(arow + kb + lk4);
        float4 bv = *(const float4*)(brow + kb + lk4);
        __syncthreads();
        As[lrow][lk4 + 0] = av.x; As[lrow][lk4 + 1] = av.y;
        As[lrow][lk4 + 2] = av.z; As[lrow][lk4 + 3] = av.w;
        Bs[lrow][lk4 + 0] = bv.x; Bs[lrow][lk4 + 1] = bv.y;
        Bs[lrow][lk4 + 2] = bv.z; Bs[lrow][lk4 + 3] = bv.w;
        __syncthreads();
#pragma unroll
        for (int kk = 0; kk < 16; kk++) {
            float a[4], b[4];
#pragma unroll
            for (int i = 0; i < 4; i++) a[i] = As[ty * 4 + i][kk];
#pragma unroll
            for (int j = 0; j < 4; j++) b[j] = Bs[tx * 4 + j][kk];
#pragma unroll
            for (int i = 0; i < 4; i++)
#pragma unroll
                for (int j = 0; j < 4; j++) acc[i][j] += a[i] * b[j];
        }
    }
#pragma unroll
    for (int i = 0; i < 4; i++)
#pragma unroll
        for (int j = 0; j < 4; j++)
            C[(size_t)(m0 + ty * 4 + i) * G4 + n0 + tx * 4 + j] =
                acc[i][j] + __ldg(bias + n0 + tx * 4 + j);
}

// ---------------- persistent encoder LSTM scan (Whh in SMEM) ----------------
#define ENC_SMEM ((8 * 4 * 1024 + 1024) * 4)
template <int WRITE_SEQ, int WRITE_LAST, int BARIDX>
__global__ void __launch_bounds__(256, 1)
enc_scan(const float* __restrict__ Whh, const float* __restrict__ G,
         float* __restrict__ seq) {
    extern __shared__ float sm[];
    float* sW = sm;
    float* sh = sm + 8 * 4 * 1024;
    int tid = threadIdx.x, wid = tid >> 5, lane = tid & 31;
    int unit = blockIdx.x * 8 + wid;
    float* wdst = sW + wid * 4096;
#pragma unroll
    for (int r = 0; r < 4; r++) {
        const float* src = Whh + (size_t)(unit + r * 1024) * 1024;
#pragma unroll
        for (int e = lane * 4; e < 1024; e += 128)
            *(float4*)(wdst + r * 1024 + e) = __ldg((const float4*)(src + e));
    }
    if (blockIdx.x == 0)
        for (int i = tid; i < HSZ; i += blockDim.x) g_h[0][i] = 0.0f;
    unsigned int epoch = 0;
    unsigned int* bar = &g_bars[BARIDX];
    gbar(bar, epoch);
    float c = 0.0f;
    int cur = 0;
    for (int t = 0; t < TXN; t++) {
        const float* gt = G + (size_t)t * G4;
        float addv = 0.0f;
        if (lane < 4) addv = __ldg(gt + unit + lane * 1024);
        *(float4*)(sh + tid * 4) = __ldcg((const float4*)(&g_h[cur][tid * 4]));
        __syncthreads();
        float a0 = 0, a1 = 0, a2 = 0, a3 = 0;
#pragma unroll
        for (int k = 0; k < 8; k++) {
            int j = (k * 32 + lane) << 2;
            float4 h4 = *(float4*)(sh + j);
            float4 w0 = *(float4*)(wdst + j);
            float4 w1 = *(float4*)(wdst + 1024 + j);
            float4 w2 = *(float4*)(wdst + 2048 + j);
            float4 w3 = *(float4*)(wdst + 3072 + j);
            a0 += w0.x * h4.x + w0.y * h4.y + w0.z * h4.z + w0.w * h4.w;
            a1 += w1.x * h4.x + w1.y * h4.y + w1.z * h4.z + w1.w * h4.w;
            a2 += w2.x * h4.x + w2.y * h4.y + w2.z * h4.z + w2.w * h4.w;
            a3 += w3.x * h4.x + w3.y * h4.y + w3.z * h4.z + w3.w * h4.w;
        }
        a0 = wredsum(a0); a1 = wredsum(a1); a2 = wredsum(a2); a3 = wredsum(a3);
        float i_, f_, gg, o_;
        gates4_f(a0, a1, a2, a3, addv, lane, i_, f_, gg, o_);
        if (lane == 0) {
            c = f_ * c + i_ * gg;
            float h = o_ * tanhf(c);
            g_h[cur ^ 1][unit] = h;
            if (WRITE_SEQ) seq[(size_t)t * HSZ + unit] = h;
            if (WRITE_LAST && t == TXN - 1) g_hlast[unit] = h;
        }
        gbar(bar, epoch);
        cur ^= 1;
    }
}

// ---------------- fc + relu (fp64, off hot path) ----------------
__global__ void fc_relu(const float* __restrict__ W, const float* __restrict__ b,
                        const float* __restrict__ in, float* __restrict__ out) {
    __shared__ double red[8];
    int r = blockIdx.x, tid = threadIdx.x, wid = tid >> 5, lane = tid & 31;
    const float* wr = W + (size_t)r * 1024;
    float4 w = __ldg((const float4*)(wr + tid * 4));
    float4 v = __ldg((const float4*)(in + tid * 4));
    double acc = (double)(w.x * v.x) + (double)(w.y * v.y) +
                 (double)(w.z * v.z) + (double)(w.w * v.w);
    acc = wredsum_d(acc);
    if (lane == 0) red[wid] = acc;
    __syncthreads();
    if (tid == 0) {
        double s = 0;
#pragma unroll
        for (int i = 0; i < 8; i++) s += red[i];
        double val = s + (double)__ldg(b + r);
        out[r] = (float)(val > 0.0 ? val : 0.0);
    }
}

// ---------------- persistent greedy decoder ----------------
#define DECT 512
__global__ void __launch_bounds__(DECT, 1)
decoder_kernel(
    const float* __restrict__ dWih0, const float* __restrict__ dWhh0, const float* __restrict__ db0,
    const float* __restrict__ dWih1, const float* __restrict__ dWhh1, const float* __restrict__ db1,
    const float* __restrict__ outw, const float* __restrict__ outb,
    const int* __restrict__ y, float* __restrict__ out) {
    __shared__ float sh0[HSZ];
    __shared__ float sh1[HSZ];
    __shared__ unsigned long long skeys[16];
    int tid = threadIdx.x, wid = tid >> 5, lane = tid & 31;
    // spread the 1024 layer units across ALL blocks (wid-major)
    int unit = wid * gridDim.x + blockIdx.x;
    unsigned int epoch = 0;
    unsigned int* bar = &g_bars[2];
    if (blockIdx.x == 0)
        for (int i = tid; i < HSZ; i += blockDim.x) {
            float v = g_hinit[i];
            g_d0[0][i] = v; g_d1[0][i] = v;
        }
    float c0 = 0.0f, c1 = 0.0f;
    if (unit < HSZ) { c0 = __ldg(&g_hinit[unit]); c1 = c0; }
    gbar(bar, epoch);
    int cur = 0;
    float xt0 = (float)__ldg(&y[0]);
    int gw = blockIdx.x * 16 + wid, nw = gridDim.x * 16;

    for (int t = 0; t < TYN - 1; t++) {
        float xt;
        if (t == 0) xt = xt0;
        else {
            unsigned long long key = __ldcg(&g_amax[t - 1]);
            xt = (float)(0xFFFFFFFFu - (unsigned int)(key & 0xFFFFFFFFull));
        }
        // ---- layer 0 ----
        if (tid < 256)
            *(float4*)(sh0 + tid * 4) = __ldcg((const float4*)(&g_d0[cur][tid * 4]));
        __syncthreads();
        if (unit < HSZ) {
            float a0 = 0, a1 = 0, a2 = 0, a3 = 0;
            const float* b = dWhh0 + (size_t)unit * 1024;
#pragma unroll
            for (int k = 0; k < 8; k++) {
                int j = (k * 32 + lane) << 2;
                float4 h4 = *(float4*)(sh0 + j);
                float4 w;
                w = __ldg((const float4*)(b + j));
                a0 += w.x * h4.x + w.y * h4.y + w.z * h4.z + w.w * h4.w;
                w = __ldg((const float4*)(b + (1 << 20) + j));
                a1 += w.x * h4.x + w.y * h4.y + w.z * h4.z + w.w * h4.w;
                w = __ldg((const float4*)(b + (2 << 20) + j));
                a2 += w.x * h4.x + w.y * h4.y + w.z * h4.z + w.w * h4.w;
                w = __ldg((const float4*)(b + (3 << 20) + j));
                a3 += w.x * h4.x + w.y * h4.y + w.z * h4.z + w.w * h4.w;
            }
            a0 = wredsum(a0); a1 = wredsum(a1); a2 = wredsum(a2); a3 = wredsum(a3);
            float addv = 0.0f;
            if (lane < 4)
                addv = __ldg(dWih0 + unit + lane * 1024) * xt + __ldg(db0 + unit + lane * 1024);
            float i_, f_, gg, o_;
            gates4_f(a0, a1, a2, a3, addv, lane, i_, f_, gg, o_);
            if (lane == 0) {
                c0 = f_ * c0 + i_ * gg;
                g_d0[cur ^ 1][unit] = o_ * tanhf(c0);
            }
        }
        gbar(bar, epoch);
        // ---- layer 1 ----
        if (tid < 256) {
            *(float4*)(sh0 + tid * 4) = __ldcg((const float4*)(&g_d0[cur ^ 1][tid * 4]));
            *(float4*)(sh1 + tid * 4) = __ldcg((const float4*)(&g_d1[cur][tid * 4]));
        }
        __syncthreads();
        if (unit < HSZ) {
            float a0 = 0, a1 = 0, a2 = 0, a3 = 0;
            const float* bi = dWih1 + (size_t)unit * 1024;
            const float* bh = dWhh1 + (size_t)unit * 1024;
#pragma unroll
            for (int k = 0; k < 8; k++) {
                int j = (k * 32 + lane) << 2;
                float4 ha = *(float4*)(sh0 + j);
                float4 hb = *(float4*)(sh1 + j);
                float4 w;
                w = __ldg((const float4*)(bi + j));
                a0 += w.x * ha.x + w.y * ha.y + w.z * ha.z + w.w * ha.w;
                w = __ldg((const float4*)(bh + j));
                a0 += w.x * hb.x + w.y * hb.y + w.z * hb.z + w.w * hb.w;
                w = __ldg((const float4*)(bi + (1 << 20) + j));
                a1 += w.x * ha.x + w.y * ha.y + w.z * ha.z + w.w * ha.w;
                w = __ldg((const float4*)(bh + (1 << 20) + j));
                a1 += w.x * hb.x + w.y * hb.y + w.z * hb.z + w.w * hb.w;
                w = __ldg((const float4*)(bi + (2 << 20) + j));
                a2 += w.x * ha.x + w.y * ha.y + w.z * ha.z + w.w * ha.w;
                w = __ldg((const float4*)(bh + (2 << 20) + j));
                a2 += w.x * hb.x + w.y * hb.y + w.z * hb.z + w.w * hb.w;
                w = __ldg((const float4*)(bi + (3 << 20) + j));
                a3 += w.x * ha.x + w.y * ha.y + w.z * ha.z + w.w * ha.w;
                w = __ldg((const float4*)(bh + (3 << 20) + j));
                a3 += w.x * hb.x + w.y * hb.y + w.z * hb.z + w.w * hb.w;
            }
            a0 = wredsum(a0); a1 = wredsum(a1); a2 = wredsum(a2); a3 = wredsum(a3);
            float addv = 0.0f;
            if (lane < 4) addv = __ldg(db1 + unit + lane * 1024);
            float i_, f_, gg, o_;
            gates4_f(a0, a1, a2, a3, addv, lane, i_, f_, gg, o_);
            if (lane == 0) {
                c1 = f_ * c1 + i_ * gg;
                g_d1[cur ^ 1][unit] = o_ * tanhf(c1);
            }
        }
        gbar(bar, epoch);
        // ---- projection: bf16 pass + per-warp-local fp32 rescue (one phase) ----
        if (tid < 256)
            *(float4*)(sh1 + tid * 4) = __ldcg((const float4*)(&g_d1[cur ^ 1][tid * 4]));
        __syncthreads();
        float bestv = -INFINITY; int besti = 0;
        float* orow = out + (size_t)(t + 1) * VSZ;
        int r = gw;
        for (; r + nw < VSZ; r += 2 * nw) {
            int r2 = r + nw;
            const uint4* wr0 = (const uint4*)(g_owbf + (size_t)r * 512);
            const uint4* wr1 = (const uint4*)(g_owbf + (size_t)r2 * 512);
            float pA0 = 0, pA1 = 0, pB0 = 0, pB1 = 0;
#pragma unroll
            for (int k = 0; k < 4; k++) {
                int q = k * 32 + lane;
                uint4 wa = __ldcs(wr0 + q);
                uint4 wb = __ldcs(wr1 + q);
                float4 h0 = *(float4*)(sh1 + 8 * q);
                float4 h1 = *(float4*)(sh1 + 8 * q + 4);
                pA0 += bflo(wa.x) * h0.x + bfhi(wa.x) * h0.y + bflo(wa.y) * h0.z + bfhi(wa.y) * h0.w;
                pA1 += bflo(wa.z) * h1.x + bfhi(wa.z) * h1.y + bflo(wa.w) * h1.z + bfhi(wa.w) * h1.w;
                pB0 += bflo(wb.x) * h0.x + bfhi(wb.x) * h0.y + bflo(wb.y) * h0.z + bfhi(wb.y) * h0.w;
                pB1 += bflo(wb.z) * h1.x + bfhi(wb.z) * h1.y + bflo(wb.w) * h1.z + bfhi(wb.w) * h1.w;
            }
            float accA = wredsum(pA0 + pA1);
            float accB = wredsum(pB0 + pB1);
            if (lane == 0) {
                float lgA = accA + __ldg(outb + r);
                float lgB = accB + __ldg(outb + r2);
                orow[r] = lgA;
                orow[r2] = lgB;
                if (lgA > bestv) { bestv = lgA; besti = r; }
                if (lgB > bestv) { bestv = lgB; besti = r2; }
            }
        }
        if (r < VSZ) {
            const uint4* wr0 = (const uint4*)(g_owbf + (size_t)r * 512);
            float p0 = 0, p1 = 0;
#pragma unroll
            for (int k = 0; k < 4; k++) {
                int q = k * 32 + lane;
                uint4 wa = __ldcs(wr0 + q);
                float4 h0 = *(float4*)(sh1 + 8 * q);
                float4 h1 = *(float4*)(sh1 + 8 * q + 4);
                p0 += bflo(wa.x) * h0.x + bfhi(wa.x) * h0.y + bflo(wa.y) * h0.z + bfhi(wa.y) * h0.w;
                p1 += bflo(wa.z) * h1.x + bfhi(wa.z) * h1.y + bflo(wa.w) * h1.z + bfhi(wa.w) * h1.w;
            }
            float acc = wredsum(p0 + p1);
            if (lane == 0) {
                float lg = acc + __ldg(outb + r);
                orow[r] = lg;
                if (lg > bestv) { bestv = lg; besti = r; }
            }
        }
        // rescue vs LOCAL best: any row within MARGIN of the global best is
        // necessarily within MARGIN of its own warp's local best.
        {
            float thresh = __shfl_sync(0xffffffffu, bestv, 0) - MARGIN;
            unsigned long long bkey2 = 0ull;
            for (int rr = gw; rr < VSZ; rr += nw) {
                float lv = 0.0f;
                if (lane == 0) lv = orow[rr];
                lv = __shfl_sync(0xffffffffu, lv, 0);
                if (lv >= thresh) {
                    const float* wrf = outw + (size_t)rr * 1024;
                    float p0 = 0, p1 = 0;
#pragma unroll
                    for (int k = 0; k < 8; k += 2) {
                        int j0 = (k * 32 + lane) << 2;
                        int j1 = ((k + 1) * 32 + lane) << 2;
                        float4 wa0 = __ldg((const float4*)(wrf + j0));
                        float4 wa1 = __ldg((const float4*)(wrf + j1));
                        float4 h40 = *(float4*)(sh1 + j0);
                        float4 h41 = *(float4*)(sh1 + j1);
                        p0 += wa0.x * h40.x + wa0.y * h40.y + wa0.z * h40.z + wa0.w * h40.w;
                        p1 += wa1.x * h41.x + wa1.y * h41.y + wa1.z * h41.z + wa1.w * h41.w;
                    }
                    float accf = wredsum(p0 + p1);
                    if (lane == 0) {
                        float lgf = accf + __ldg(outb + rr);
                        orow[rr] = lgf;
                        unsigned long long kk = mkkey(lgf, rr);
                        if (kk > bkey2) bkey2 = kk;
                    }
                }
            }
            if (lane == 0) skeys[wid] = bkey2;
        }
        __syncthreads();
        if (tid == 0) {
            unsigned long long k0 = skeys[0];
#pragma unroll
            for (int w = 1; w < 16; w++) if (skeys[w] > k0) k0 = skeys[w];
            atomicMax(&g_amax[t], k0);
        }
        gbar(bar, epoch);
        cur ^= 1;
    }
}

// ---------------- final log_softmax over rows (in place) ----------------
__global__ void logsoftmax_kernel(float* __restrict__ out) {
    int row = blockIdx.x, tid = threadIdx.x, wid = tid >> 5, lane = tid & 31;
    float* p = out + (size_t)row * VSZ;
    if (row == 0) {
        float v = -(float)log((double)VSZ);
        for (int i = tid; i < VSZ; i += blockDim.x) p[i] = v;
        return;
    }
    __shared__ double redd[8];
    __shared__ float redf[8];
    __shared__ float bcf;
    __shared__ double bcd;
    float m = -INFINITY;
    for (int i = tid; i < VSZ; i += blockDim.x) m = fmaxf(m, p[i]);
#pragma unroll
    for (int o = 16; o; o >>= 1) m = fmaxf(m, __shfl_xor_sync(0xffffffffu, m, o));
    if (lane == 0) redf[wid] = m;
    __syncthreads();
    if (tid == 0) {
        float mm = redf[0];
#pragma unroll
        for (int i = 1; i < 8; i++) mm = fmaxf(mm, redf[i]);
        bcf = mm;
    }
    __syncthreads();
    m = bcf;
    double s = 0;
    for (int i = tid; i < VSZ; i += blockDim.x) s += (double)expf(p[i] - m);
    s = wredsum_d(s);
    if (lane == 0) redd[wid] = s;
    __syncthreads();
    if (tid == 0) {
        double ss = 0;
#pragma unroll
        for (int i = 0; i < 8; i++) ss += redd[i];
        bcd = (double)m + log(ss);
    }
    __syncthreads();
    double lse = bcd;
    for (int i = tid; i < VSZ; i += blockDim.x) p[i] = (float)((double)p[i] - lse);
}

// ---------------- launch ----------------
extern "C" void kernel_launch(void* const* d_in, const int* in_sizes, int n_in,
                              void* d_out, int out_size) {
    const int*   x     = (const int*)d_in[0];
    const int*   y     = (const int*)d_in[1];
    const float* emb   = (const float*)d_in[2];
    const float* eWih0 = (const float*)d_in[3];
    const float* eWhh0 = (const float*)d_in[4];
    const float* eb0   = (const float*)d_in[5];
    const float* eWih1 = (const float*)d_in[6];
    const float* eWhh1 = (const float*)d_in[7];
    const float* eb1   = (const float*)d_in[8];
    const float* fc1w  = (const float*)d_in[9];
    const float* fc1b  = (const float*)d_in[10];
    const float* fc2w  = (const float*)d_in[11];
    const float* fc2b  = (const float*)d_in[12];
    const float* dWih0 = (const float*)d_in[13];
    const float* dWhh0 = (const float*)d_in[14];
    const float* db0   = (const float*)d_in[15];
    const float* dWih1 = (const float*)d_in[16];
    const float* dWhh1 = (const float*)d_in[17];
    const float* db1   = (const float*)d_in[18];
    const float* outw  = (const float*)d_in[19];
    const float* outb  = (const float*)d_in[20];
    float* out = (float*)d_out;

    float *pG = nullptr, *pSeq = nullptr, *pF1 = nullptr, *pHinit = nullptr, *pHlast = nullptr;
    cudaGetSymbolAddress((void**)&pG, g_G);
    cudaGetSymbolAddress((void**)&pSeq, g_seq);
    cudaGetSymbolAddress((void**)&pF1, g_f1);
    cudaGetSymbolAddress((void**)&pHinit, g_hinit);
    cudaGetSymbolAddress((void**)&pHlast, g_hlast);

    int dev = 0, nsm = 148;
    cudaGetDevice(&dev);
    cudaDeviceGetAttribute(&nsm, cudaDevAttrMultiProcessorCount, dev);
    if (nsm < 128) nsm = 128;

    cudaFuncSetAttribute(enc_scan<1, 0, 0>, cudaFuncAttributeMaxDynamicSharedMemorySize, ENC_SMEM);
    cudaFuncSetAttribute(enc_scan<0, 1, 1>, cudaFuncAttributeMaxDynamicSharedMemorySize, ENC_SMEM);

    init_kernel<<<1, 512>>>();
    conv_bf16<<<VSZ * (HSZ / 4) / 256, 256>>>(outw);
    gemm_nt<ESZ><<<dim3(64, 32), 256>>>(emb, x, eWih0, eb0, pG);
    enc_scan<1, 0, 0><<<128, 256, ENC_SMEM>>>(eWhh0, pG, pSeq);
    gemm_nt<HSZ><<<dim3(64, 32), 256>>>(pSeq, nullptr, eWih1, eb1, pG);
    enc_scan<0, 1, 1><<<128, 256, ENC_SMEM>>>(eWhh1, pG, nullptr);
    fc_relu<<<1024, 256>>>(fc1w, fc1b, pHlast, pF1);
    fc_relu<<<1024, 256>>>(fc2w, fc2b, pF1, pHinit);
    decoder_kernel<<<nsm, DECT>>>(dWih0, dWhh0, db0, dWih1, dWhh1, db1, outw, outb, y, out);
    logsoftmax_kernel<<<TYN, 256>>>(out);
}

// round 11
// speedup vs baseline: 6.1871x; 1.0473x over previous
#include <cuda_runtime.h>
#include <cuda_bf16.h>
#include <math.h>

// ---------------- problem constants ----------------
#define VSZ   32000
#define ESZ   512
#define HSZ   1024
#define TXN   2048
#define TYN   512
#define G4    4096
#define MARGIN 0.03f

// ---------------- device scratch ----------------
// G layout: [blk(128)][t(2048)][gate(4)][ui(8)]  (one 128B line per block-step)
__device__ float g_G[(size_t)TXN * G4];
__device__ float g_seq[(size_t)TXN * HSZ];
__device__ unsigned g_owbf[(size_t)VSZ * HSZ / 2];   // bf16 out_w (65.5MB)
__device__ float g_h[2][HSZ];
__device__ float g_hlast[HSZ];
__device__ float g_f1[HSZ];
__device__ float g_hinit[HSZ];
__device__ float g_aw0[2][G4];                 // Whh0@h0 pre-activations, double buffered
__device__ float g_d1f[HSZ];                   // decoder layer1 h
__device__ unsigned long long g_amax[TYN - 1];
__device__ unsigned int g_bars[4];

// ---------------- helpers ----------------
__device__ __forceinline__ float wredsum(float v) {
#pragma unroll
    for (int o = 16; o; o >>= 1) v += __shfl_xor_sync(0xffffffffu, v, o);
    return v;
}
__device__ __forceinline__ double wredsum_d(double v) {
#pragma unroll
    for (int o = 16; o; o >>= 1) v += __shfl_xor_sync(0xffffffffu, v, o);
    return v;
}
__device__ __forceinline__ float bflo(unsigned u) { return __uint_as_float(u << 16); }
__device__ __forceinline__ float bfhi(unsigned u) { return __uint_as_float(u & 0xFFFF0000u); }

__device__ __forceinline__ unsigned long long mkkey(float v, int idx) {
    unsigned u = __float_as_uint(v);
    u = (u & 0x80000000u) ? ~u : (u | 0x80000000u);
    return ((unsigned long long)u << 32) |
           (unsigned long long)(0xFFFFFFFFu - (unsigned)idx);
}

__device__ __forceinline__ void gates4_f(float a0, float a1, float a2, float a3,
                                         float addv, int lane,
                                         float& i_, float& f_, float& g_, float& o_) {
    float asel = (lane == 0) ? a0 : (lane == 1) ? a1 : (lane == 2) ? a2 : a3;
    float gv = 0.0f;
    if (lane < 4) {
        float x = asel + addv;
        gv = (lane == 2) ? tanhf(x) : 1.0f / (1.0f + expf(-x));
    }
    i_ = __shfl_sync(0xffffffffu, gv, 0);
    f_ = __shfl_sync(0xffffffffu, gv, 1);
    g_ = __shfl_sync(0xffffffffu, gv, 2);
    o_ = __shfl_sync(0xffffffffu, gv, 3);
}

// release/acquire software grid barrier
__device__ __forceinline__ void gbar(unsigned int* cnt, unsigned int& epoch) {
    epoch += gridDim.x;
    __syncthreads();
    if (threadIdx.x == 0) {
        asm volatile("red.release.gpu.global.add.u32 [%0], %1;"
                     :: "l"(cnt), "r"(1u) : "memory");
        unsigned cur;
        do {
            asm volatile("ld.acquire.gpu.global.u32 %0, [%1];"
                         : "=r"(cur) : "l"(cnt) : "memory");
        } while ((int)(cur - epoch) < 0);
    }
    __syncthreads();
}

// ---------------- init ----------------
__global__ void init_kernel() {
    int i = threadIdx.x;
    if (i < 4) g_bars[i] = 0u;
    for (int j = i; j < TYN - 1; j += blockDim.x) g_amax[j] = 0ull;
}

// ---------------- out_w fp32 -> bf16 (one-time) ----------------
__global__ void conv_bf16(const float* __restrict__ w) {
    size_t i = (size_t)blockIdx.x * blockDim.x + threadIdx.x;
    float4 v = *(const float4*)(w + i * 4);
    unsigned b0 = (unsigned)__bfloat16_as_ushort(__float2bfloat16_rn(v.x)) |
                  ((unsigned)__bfloat16_as_ushort(__float2bfloat16_rn(v.y)) << 16);
    unsigned b1 = (unsigned)__bfloat16_as_ushort(__float2bfloat16_rn(v.z)) |
                  ((unsigned)__bfloat16_as_ushort(__float2bfloat16_rn(v.w)) << 16);
    g_owbf[i * 2] = b0;
    g_owbf[i * 2 + 1] = b1;
}

// ---------------- tiled GEMM (fp32) with TRANSPOSED block-major output ----------------
// out index: blk*(2048*32) + t*32 + gate*8 + ui  where n = gate*1024 + blk*8 + ui
template <int KDIM>
__global__ void gemm_nt(const float* __restrict__ A, const int* __restrict__ ridx,
                        const float* __restrict__ B, const float* __restrict__ bias,
                        float* __restrict__ C) {
    __shared__ float As[64][17];
    __shared__ float Bs[64][17];
    int tid = threadIdx.x;
    int m0 = blockIdx.y * 64, n0 = blockIdx.x * 64;
    int tx = tid & 15, ty = tid >> 4;
    int lrow = tid >> 2;
    int lk4 = (tid & 3) * 4;
    const float* arow = A + (size_t)(ridx ? ridx[m0 + lrow] : (m0 + lrow)) * KDIM;
    const float* brow = B + (size_t)(n0 + lrow) * KDIM;
    float acc[4][4] = {};
    for (int kb = 0; kb < KDIM; kb += 16) {
        float4 av = *(const float4*)(arow + kb + lk4);
        float4 bv = *(const float4*)(brow + kb + lk4);
        __syncthreads();
        As[lrow][lk4 + 0] = av.x; As[lrow][lk4 + 1] = av.y;
        As[lrow][lk4 + 2] = av.z; As[lrow][lk4 + 3] = av.w;
        Bs[lrow][lk4 + 0] = bv.x; Bs[lrow][lk4 + 1] = bv.y;
        Bs[lrow][lk4 + 2] = bv.z; Bs[lrow][lk4 + 3] = bv.w;
        __syncthreads();
#pragma unroll
        for (int kk = 0; kk < 16; kk++) {
            float a[4], b[4];
#pragma unroll
            for (int i = 0; i < 4; i++) a[i] = As[ty * 4 + i][kk];
#pragma unroll
            for (int j = 0; j < 4; j++) b[j] = Bs[tx * 4 + j][kk];
#pragma unroll
            for (int i = 0; i < 4; i++)
#pragma unroll
                for (int j = 0; j < 4; j++) acc[i][j] += a[i] * b[j];
        }
    }
    int nb = n0 + tx * 4;
    int gate = nb >> 10;
    int u = nb & 1023;
    int blk = u >> 3, ui = u & 7;          // ui in {0,4}, j spans 4 consecutive
    float4 b4 = __ldg((const float4*)(bias + nb));
    float* cb = C + (size_t)blk * (TXN * 32) + gate * 8 + ui;
#pragma unroll
    for (int i = 0; i < 4; i++) {
        int m = m0 + ty * 4 + i;
        float4 v = make_float4(acc[i][0] + b4.x, acc[i][1] + b4.y,
                               acc[i][2] + b4.z, acc[i][3] + b4.w);
        *(float4*)(cb + (size_t)m * 32) = v;
    }
}

// ---------------- persistent encoder LSTM scan (Whh in SMEM) ----------------
#define ENC_SMEM ((8 * 4 * 1024 + 1024) * 4)
template <int WRITE_SEQ, int WRITE_LAST, int BARIDX>
__global__ void __launch_bounds__(256, 1)
enc_scan(const float* __restrict__ Whh, const float* __restrict__ G,
         float* __restrict__ seq) {
    extern __shared__ float sm[];
    float* sW = sm;
    float* sh = sm + 8 * 4 * 1024;
    int tid = threadIdx.x, wid = tid >> 5, lane = tid & 31;
    int unit = blockIdx.x * 8 + wid;
    float* wdst = sW + wid * 4096;
#pragma unroll
    for (int r = 0; r < 4; r++) {
        const float* src = Whh + (size_t)(unit + r * 1024) * 1024;
#pragma unroll
        for (int e = lane * 4; e < 1024; e += 128)
            *(float4*)(wdst + r * 1024 + e) = __ldg((const float4*)(src + e));
    }
    if (blockIdx.x == 0)
        for (int i = tid; i < HSZ; i += blockDim.x) g_h[0][i] = 0.0f;
    unsigned int epoch = 0;
    unsigned int* bar = &g_bars[BARIDX];
    const float* gp = G + (size_t)blockIdx.x * (TXN * 32);
    gbar(bar, epoch);
    float c = 0.0f;
    int cur = 0;
    for (int t = 0; t < TXN; t++) {
        float addv = 0.0f;
        if (lane < 4) addv = __ldg(gp + t * 32 + lane * 8 + wid);
        if (lane == 4 && t + 16 < TXN)
            asm volatile("prefetch.global.L2 [%0];" :: "l"(gp + (t + 16) * 32));
        *(float4*)(sh + tid * 4) = __ldcg((const float4*)(&g_h[cur][tid * 4]));
        __syncthreads();
        float a0 = 0, a1 = 0, a2 = 0, a3 = 0;
#pragma unroll
        for (int k = 0; k < 8; k++) {
            int j = (k * 32 + lane) << 2;
            float4 h4 = *(float4*)(sh + j);
            float4 w0 = *(float4*)(wdst + j);
            float4 w1 = *(float4*)(wdst + 1024 + j);
            float4 w2 = *(float4*)(wdst + 2048 + j);
            float4 w3 = *(float4*)(wdst + 3072 + j);
            a0 += w0.x * h4.x + w0.y * h4.y + w0.z * h4.z + w0.w * h4.w;
            a1 += w1.x * h4.x + w1.y * h4.y + w1.z * h4.z + w1.w * h4.w;
            a2 += w2.x * h4.x + w2.y * h4.y + w2.z * h4.z + w2.w * h4.w;
            a3 += w3.x * h4.x + w3.y * h4.y + w3.z * h4.z + w3.w * h4.w;
        }
        a0 = wredsum(a0); a1 = wredsum(a1); a2 = wredsum(a2); a3 = wredsum(a3);
        float i_, f_, gg, o_;
        gates4_f(a0, a1, a2, a3, addv, lane, i_, f_, gg, o_);
        if (lane == 0) {
            c = f_ * c + i_ * gg;
            float h = o_ * tanhf(c);
            g_h[cur ^ 1][unit] = h;
            if (WRITE_SEQ) seq[(size_t)t * HSZ + unit] = h;
            if (WRITE_LAST && t == TXN - 1) g_hlast[unit] = h;
        }
        gbar(bar, epoch);
        cur ^= 1;
    }
}

// ---------------- fc + relu (fp64, off hot path) ----------------
__global__ void fc_relu(const float* __restrict__ W, const float* __restrict__ b,
                        const float* __restrict__ in, float* __restrict__ out) {
    __shared__ double red[8];
    int r = blockIdx.x, tid = threadIdx.x, wid = tid >> 5, lane = tid & 31;
    const float* wr = W + (size_t)r * 1024;
    float4 w = __ldg((const float4*)(wr + tid * 4));
    float4 v = __ldg((const float4*)(in + tid * 4));
    double acc = (double)(w.x * v.x) + (double)(w.y * v.y) +
                 (double)(w.z * v.z) + (double)(w.w * v.w);
    acc = wredsum_d(acc);
    if (lane == 0) red[wid] = acc;
    __syncthreads();
    if (tid == 0) {
        double s = 0;
#pragma unroll
        for (int i = 0; i < 8; i++) s += red[i];
        double val = s + (double)__ldg(b + r);
        out[r] = (float)(val > 0.0 ? val : 0.0);
    }
}

// ---------------- persistent greedy decoder ----------------
// Per step: phase A (local, replicated layer0) -> phase B (Wih1@h0 + Whh0@h0
// precompute, gates1) -> barB -> phase C (Whh1@h1 precompute + bf16 projection
// + fp32 rescue + argmax) -> barC.  Only 2 grid barriers per step.
#define DECT 512
__global__ void __launch_bounds__(DECT, 1)
decoder_kernel(
    const float* __restrict__ dWih0, const float* __restrict__ dWhh0, const float* __restrict__ db0,
    const float* __restrict__ dWih1, const float* __restrict__ dWhh1, const float* __restrict__ db1,
    const float* __restrict__ outw, const float* __restrict__ outb,
    const int* __restrict__ y, float* __restrict__ out) {
    __shared__ float sh0[HSZ];
    __shared__ float sh1[HSZ];
    __shared__ float c0s[HSZ];
    __shared__ float wih0s[G4];
    __shared__ float b0s[G4];
    __shared__ unsigned long long skeys[16];
    int tid = threadIdx.x, wid = tid >> 5, lane = tid & 31;
    int unit = wid * gridDim.x + blockIdx.x;        // layer-1/precompute owner
    unsigned int epoch = 0;
    unsigned int* bar = &g_bars[2];

    for (int i = tid; i < G4; i += DECT) {
        wih0s[i] = __ldg(dWih0 + i);
        b0s[i] = __ldg(db0 + i);
    }
    for (int i = tid; i < HSZ; i += DECT) {
        float v = __ldg(&g_hinit[i]);
        c0s[i] = v;
        sh0[i] = v;                                  // h_init for pre-phase matvecs
    }
    __syncthreads();

    float c1 = 0.0f;
    if (unit < HSZ) c1 = __ldg(&g_hinit[unit]);

    // ---- pre-phase: aw0[0] = Whh0@h_init (publish), ah1p = Whh1@h_init (regs) ----
    float ah1p0 = 0, ah1p1 = 0, ah1p2 = 0, ah1p3 = 0;
    if (unit < HSZ) {
        float w0 = 0, w1 = 0, w2 = 0, w3 = 0;
        const float* bh0 = dWhh0 + (size_t)unit * 1024;
        const float* bh1 = dWhh1 + (size_t)unit * 1024;
#pragma unroll
        for (int k = 0; k < 8; k++) {
            int j = (k * 32 + lane) << 2;
            float4 h4 = *(float4*)(sh0 + j);
            float4 w;
            w = __ldg((const float4*)(bh0 + j));
            w0 += w.x * h4.x + w.y * h4.y + w.z * h4.z + w.w * h4.w;
            w = __ldg((const float4*)(bh0 + (1 << 20) + j));
            w1 += w.x * h4.x + w.y * h4.y + w.z * h4.z + w.w * h4.w;
            w = __ldg((const float4*)(bh0 + (2 << 20) + j));
            w2 += w.x * h4.x + w.y * h4.y + w.z * h4.z + w.w * h4.w;
            w = __ldg((const float4*)(bh0 + (3 << 20) + j));
            w3 += w.x * h4.x + w.y * h4.y + w.z * h4.z + w.w * h4.w;
            w = __ldg((const float4*)(bh1 + j));
            ah1p0 += w.x * h4.x + w.y * h4.y + w.z * h4.z + w.w * h4.w;
            w = __ldg((const float4*)(bh1 + (1 << 20) + j));
            ah1p1 += w.x * h4.x + w.y * h4.y + w.z * h4.z + w.w * h4.w;
            w = __ldg((const float4*)(bh1 + (2 << 20) + j));
            ah1p2 += w.x * h4.x + w.y * h4.y + w.z * h4.z + w.w * h4.w;
            w = __ldg((const float4*)(bh1 + (3 << 20) + j));
            ah1p3 += w.x * h4.x + w.y * h4.y + w.z * h4.z + w.w * h4.w;
        }
        w0 = wredsum(w0); w1 = wredsum(w1); w2 = wredsum(w2); w3 = wredsum(w3);
        ah1p0 = wredsum(ah1p0); ah1p1 = wredsum(ah1p1);
        ah1p2 = wredsum(ah1p2); ah1p3 = wredsum(ah1p3);
        float wsel = (lane == 0) ? w0 : (lane == 1) ? w1 : (lane == 2) ? w2 : w3;
        if (lane < 4) g_aw0[0][lane * 1024 + unit] = wsel;
    }
    gbar(bar, epoch);

    float xt0 = (float)__ldg(&y[0]);
    int gw = blockIdx.x * 16 + wid, nw = gridDim.x * 16;

    for (int t = 0; t < TYN - 1; t++) {
        float xt;
        if (t == 0) xt = xt0;
        else {
            unsigned long long key = __ldcg(&g_amax[t - 1]);
            xt = (float)(0xFFFFFFFFu - (unsigned int)(key & 0xFFFFFFFFull));
        }
        // ---- phase A: replicated layer0 (local only) ----
        {
            const float* aw = &g_aw0[t & 1][0];
#pragma unroll
            for (int uu = 0; uu < 2; uu++) {
                int u = tid + uu * DECT;
                float x0 = __ldcg(aw + u)        + (wih0s[u] * xt        + b0s[u]);
                float x1 = __ldcg(aw + 1024 + u) + (wih0s[1024 + u] * xt + b0s[1024 + u]);
                float x2 = __ldcg(aw + 2048 + u) + (wih0s[2048 + u] * xt + b0s[2048 + u]);
                float x3 = __ldcg(aw + 3072 + u) + (wih0s[3072 + u] * xt + b0s[3072 + u]);
                float i_ = 1.0f / (1.0f + expf(-x0));
                float f_ = 1.0f / (1.0f + expf(-x1));
                float gg = tanhf(x2);
                float o_ = 1.0f / (1.0f + expf(-x3));
                float c = f_ * c0s[u] + i_ * gg;
                c0s[u] = c;
                sh0[u] = o_ * tanhf(c);
            }
        }
        __syncthreads();
        // ---- phase B: Wih1@h0 + Whh0@h0 (publish for t+1), gates1 -> h1 ----
        if (unit < HSZ) {
            float ai0 = 0, ai1 = 0, ai2 = 0, ai3 = 0;
            float w0 = 0, w1 = 0, w2 = 0, w3 = 0;
            const float* bi = dWih1 + (size_t)unit * 1024;
            const float* bh0 = dWhh0 + (size_t)unit * 1024;
#pragma unroll
            for (int k = 0; k < 8; k++) {
                int j = (k * 32 + lane) << 2;
                float4 h4 = *(float4*)(sh0 + j);
                float4 w;
                w = __ldg((const float4*)(bi + j));
                ai0 += w.x * h4.x + w.y * h4.y + w.z * h4.z + w.w * h4.w;
                w = __ldg((const float4*)(bi + (1 << 20) + j));
                ai1 += w.x * h4.x + w.y * h4.y + w.z * h4.z + w.w * h4.w;
                w = __ldg((const float4*)(bi + (2 << 20) + j));
                ai2 += w.x * h4.x + w.y * h4.y + w.z * h4.z + w.w * h4.w;
                w = __ldg((const float4*)(bi + (3 << 20) + j));
                ai3 += w.x * h4.x + w.y * h4.y + w.z * h4.z + w.w * h4.w;
                w = __ldg((const float4*)(bh0 + j));
                w0 += w.x * h4.x + w.y * h4.y + w.z * h4.z + w.w * h4.w;
                w = __ldg((const float4*)(bh0 + (1 << 20) + j));
                w1 += w.x * h4.x + w.y * h4.y + w.z * h4.z + w.w * h4.w;
                w = __ldg((const float4*)(bh0 + (2 << 20) + j));
                w2 += w.x * h4.x + w.y * h4.y + w.z * h4.z + w.w * h4.w;
                w = __ldg((const float4*)(bh0 + (3 << 20) + j));
                w3 += w.x * h4.x + w.y * h4.y + w.z * h4.z + w.w * h4.w;
            }
            ai0 = wredsum(ai0); ai1 = wredsum(ai1); ai2 = wredsum(ai2); ai3 = wredsum(ai3);
            w0 = wredsum(w0); w1 = wredsum(w1); w2 = wredsum(w2); w3 = wredsum(w3);
            float wsel = (lane == 0) ? w0 : (lane == 1) ? w1 : (lane == 2) ? w2 : w3;
            if (lane < 4) g_aw0[(t + 1) & 1][lane * 1024 + unit] = wsel;
            float addv = 0.0f;
            if (lane < 4) {
                float ap = (lane == 0) ? ah1p0 : (lane == 1) ? ah1p1
                         : (lane == 2) ? ah1p2 : ah1p3;
                addv = ap + __ldg(db1 + unit + lane * 1024);
            }
            float i_, f_, gg, o_;
            gates4_f(ai0, ai1, ai2, ai3, addv, lane, i_, f_, gg, o_);
            if (lane == 0) {
                c1 = f_ * c1 + i_ * gg;
                g_d1f[unit] = o_ * tanhf(c1);
            }
        }
        gbar(bar, epoch);
        // ---- phase C: Whh1@h1 precompute + bf16 projection + rescue + argmax ----
        if (tid < 256)
            *(float4*)(sh1 + tid * 4) = __ldcg((const float4*)(&g_d1f[tid * 4]));
        __syncthreads();
        if (unit < HSZ) {
            ah1p0 = 0; ah1p1 = 0; ah1p2 = 0; ah1p3 = 0;
            const float* bh1 = dWhh1 + (size_t)unit * 1024;
#pragma unroll
            for (int k = 0; k < 8; k++) {
                int j = (k * 32 + lane) << 2;
                float4 h4 = *(float4*)(sh1 + j);
                float4 w;
                w = __ldg((const float4*)(bh1 + j));
                ah1p0 += w.x * h4.x + w.y * h4.y + w.z * h4.z + w.w * h4.w;
                w = __ldg((const float4*)(bh1 + (1 << 20) + j));
                ah1p1 += w.x * h4.x + w.y * h4.y + w.z * h4.z + w.w * h4.w;
                w = __ldg((const float4*)(bh1 + (2 << 20) + j));
                ah1p2 += w.x * h4.x + w.y * h4.y + w.z * h4.z + w.w * h4.w;
                w = __ldg((const float4*)(bh1 + (3 << 20) + j));
                ah1p3 += w.x * h4.x + w.y * h4.y + w.z * h4.z + w.w * h4.w;
            }
            ah1p0 = wredsum(ah1p0); ah1p1 = wredsum(ah1p1);
            ah1p2 = wredsum(ah1p2); ah1p3 = wredsum(ah1p3);
        }
        float bestv = -INFINITY; int besti = 0;
        float* orow = out + (size_t)(t + 1) * VSZ;
        int r = gw;
        for (; r + nw < VSZ; r += 2 * nw) {
            int r2 = r + nw;
            const uint4* wr0 = (const uint4*)(g_owbf + (size_t)r * 512);
            const uint4* wr1 = (const uint4*)(g_owbf + (size_t)r2 * 512);
            float pA0 = 0, pA1 = 0, pB0 = 0, pB1 = 0;
#pragma unroll
            for (int k = 0; k < 4; k++) {
                int q = k * 32 + lane;
                uint4 wa = __ldcs(wr0 + q);
                uint4 wb = __ldcs(wr1 + q);
                float4 h0 = *(float4*)(sh1 + 8 * q);
                float4 h1 = *(float4*)(sh1 + 8 * q + 4);
                pA0 += bflo(wa.x) * h0.x + bfhi(wa.x) * h0.y + bflo(wa.y) * h0.z + bfhi(wa.y) * h0.w;
                pA1 += bflo(wa.z) * h1.x + bfhi(wa.z) * h1.y + bflo(wa.w) * h1.z + bfhi(wa.w) * h1.w;
                pB0 += bflo(wb.x) * h0.x + bfhi(wb.x) * h0.y + bflo(wb.y) * h0.z + bfhi(wb.y) * h0.w;
                pB1 += bflo(wb.z) * h1.x + bfhi(wb.z) * h1.y + bflo(wb.w) * h1.z + bfhi(wb.w) * h1.w;
            }
            float accA = wredsum(pA0 + pA1);
            float accB = wredsum(pB0 + pB1);
            if (lane == 0) {
                float lgA = accA + __ldg(outb + r);
                float lgB = accB + __ldg(outb + r2);
                orow[r] = lgA;
                orow[r2] = lgB;
                if (lgA > bestv) { bestv = lgA; besti = r; }
                if (lgB > bestv) { bestv = lgB; besti = r2; }
            }
        }
        if (r < VSZ) {
            const uint4* wr0 = (const uint4*)(g_owbf + (size_t)r * 512);
            float p0 = 0, p1 = 0;
#pragma unroll
            for (int k = 0; k < 4; k++) {
                int q = k * 32 + lane;
                uint4 wa = __ldcs(wr0 + q);
                float4 h0 = *(float4*)(sh1 + 8 * q);
                float4 h1 = *(float4*)(sh1 + 8 * q + 4);
                p0 += bflo(wa.x) * h0.x + bfhi(wa.x) * h0.y + bflo(wa.y) * h0.z + bfhi(wa.y) * h0.w;
                p1 += bflo(wa.z) * h1.x + bfhi(wa.z) * h1.y + bflo(wa.w) * h1.z + bfhi(wa.w) * h1.w;
            }
            float acc = wredsum(p0 + p1);
            if (lane == 0) {
                float lg = acc + __ldg(outb + r);
                orow[r] = lg;
                if (lg > bestv) { bestv = lg; besti = r; }
            }
        }
        // fp32 rescue vs warp-local best
        {
            float thresh = __shfl_sync(0xffffffffu, bestv, 0) - MARGIN;
            unsigned long long bkey2 = 0ull;
            for (int rr = gw; rr < VSZ; rr += nw) {
                float lv = 0.0f;
                if (lane == 0) lv = orow[rr];
                lv = __shfl_sync(0xffffffffu, lv, 0);
                if (lv >= thresh) {
                    const float* wrf = outw + (size_t)rr * 1024;
                    float p0 = 0, p1 = 0;
#pragma unroll
                    for (int k = 0; k < 8; k += 2) {
                        int j0 = (k * 32 + lane) << 2;
                        int j1 = ((k + 1) * 32 + lane) << 2;
                        float4 wa0 = __ldg((const float4*)(wrf + j0));
                        float4 wa1 = __ldg((const float4*)(wrf + j1));
                        float4 h40 = *(float4*)(sh1 + j0);
                        float4 h41 = *(float4*)(sh1 + j1);
                        p0 += wa0.x * h40.x + wa0.y * h40.y + wa0.z * h40.z + wa0.w * h40.w;
                        p1 += wa1.x * h41.x + wa1.y * h41.y + wa1.z * h41.z + wa1.w * h41.w;
                    }
                    float accf = wredsum(p0 + p1);
                    if (lane == 0) {
                        float lgf = accf + __ldg(outb + rr);
                        orow[rr] = lgf;
                        unsigned long long kk = mkkey(lgf, rr);
                        if (kk > bkey2) bkey2 = kk;
                    }
                }
            }
            if (lane == 0) skeys[wid] = bkey2;
        }
        __syncthreads();
        if (tid == 0) {
            unsigned long long k0 = skeys[0];
#pragma unroll
            for (int w = 1; w < 16; w++) if (skeys[w] > k0) k0 = skeys[w];
            atomicMax(&g_amax[t], k0);
        }
        gbar(bar, epoch);
    }
}

// ---------------- final log_softmax over rows (in place) ----------------
__global__ void logsoftmax_kernel(float* __restrict__ out) {
    int row = blockIdx.x, tid = threadIdx.x, wid = tid >> 5, lane = tid & 31;
    float* p = out + (size_t)row * VSZ;
    if (row == 0) {
        float v = -(float)log((double)VSZ);
        for (int i = tid; i < VSZ; i += blockDim.x) p[i] = v;
        return;
    }
    __shared__ double redd[8];
    __shared__ float redf[8];
    __shared__ float bcf;
    __shared__ double bcd;
    float m = -INFINITY;
    for (int i = tid; i < VSZ; i += blockDim.x) m = fmaxf(m, p[i]);
#pragma unroll
    for (int o = 16; o; o >>= 1) m = fmaxf(m, __shfl_xor_sync(0xffffffffu, m, o));
    if (lane == 0) redf[wid] = m;
    __syncthreads();
    if (tid == 0) {
        float mm = redf[0];
#pragma unroll
        for (int i = 1; i < 8; i++) mm = fmaxf(mm, redf[i]);
        bcf = mm;
    }
    __syncthreads();
    m = bcf;
    double s = 0;
    for (int i = tid; i < VSZ; i += blockDim.x) s += (double)expf(p[i] - m);
    s = wredsum_d(s);
    if (lane == 0) redd[wid] = s;
    __syncthreads();
    if (tid == 0) {
        double ss = 0;
#pragma unroll
        for (int i = 0; i < 8; i++) ss += redd[i];
        bcd = (double)m + log(ss);
    }
    __syncthreads();
    double lse = bcd;
    for (int i = tid; i < VSZ; i += blockDim.x) p[i] = (float)((double)p[i] - lse);
}

// ---------------- launch ----------------
extern "C" void kernel_launch(void* const* d_in, const int* in_sizes, int n_in,
                              void* d_out, int out_size) {
    const int*   x     = (const int*)d_in[0];
    const int*   y     = (const int*)d_in[1];
    const float* emb   = (const float*)d_in[2];
    const float* eWih0 = (const float*)d_in[3];
    const float* eWhh0 = (const float*)d_in[4];
    const float* eb0   = (const float*)d_in[5];
    const float* eWih1 = (const float*)d_in[6];
    const float* eWhh1 = (const float*)d_in[7];
    const float* eb1   = (const float*)d_in[8];
    const float* fc1w  = (const float*)d_in[9];
    const float* fc1b  = (const float*)d_in[10];
    const float* fc2w  = (const float*)d_in[11];
    const float* fc2b  = (const float*)d_in[12];
    const float* dWih0 = (const float*)d_in[13];
    const float* dWhh0 = (const float*)d_in[14];
    const float* db0   = (const float*)d_in[15];
    const float* dWih1 = (const float*)d_in[16];
    const float* dWhh1 = (const float*)d_in[17];
    const float* db1   = (const float*)d_in[18];
    const float* outw  = (const float*)d_in[19];
    const float* outb  = (const float*)d_in[20];
    float* out = (float*)d_out;

    float *pG = nullptr, *pSeq = nullptr, *pF1 = nullptr, *pHinit = nullptr, *pHlast = nullptr;
    cudaGetSymbolAddress((void**)&pG, g_G);
    cudaGetSymbolAddress((void**)&pSeq, g_seq);
    cudaGetSymbolAddress((void**)&pF1, g_f1);
    cudaGetSymbolAddress((void**)&pHinit, g_hinit);
    cudaGetSymbolAddress((void**)&pHlast, g_hlast);

    int dev = 0, nsm = 148;
    cudaGetDevice(&dev);
    cudaDeviceGetAttribute(&nsm, cudaDevAttrMultiProcessorCount, dev);
    if (nsm < 128) nsm = 128;

    cudaFuncSetAttribute(enc_scan<1, 0, 0>, cudaFuncAttributeMaxDynamicSharedMemorySize, ENC_SMEM);
    cudaFuncSetAttribute(enc_scan<0, 1, 1>, cudaFuncAttributeMaxDynamicSharedMemorySize, ENC_SMEM);

    init_kernel<<<1, 512>>>();
    conv_bf16<<<VSZ * (HSZ / 4) / 256, 256>>>(outw);
    gemm_nt<ESZ><<<dim3(64, 32), 256>>>(emb, x, eWih0, eb0, pG);
    enc_scan<1, 0, 0><<<128, 256, ENC_SMEM>>>(eWhh0, pG, pSeq);
    gemm_nt<HSZ><<<dim3(64, 32), 256>>>(pSeq, nullptr, eWih1, eb1, pG);
    enc_scan<0, 1, 1><<<128, 256, ENC_SMEM>>>(eWhh1, pG, nullptr);
    fc_relu<<<1024, 256>>>(fc1w, fc1b, pHlast, pF1);
    fc_relu<<<1024, 256>>>(fc2w, fc2b, pF1, pHinit);
    decoder_kernel<<<nsm, DECT>>>(dWih0, dWhh0, db0, dWih1, dWhh1, db1, outw, outb, y, out);
    logsoftmax_kernel<<<TYN, 256>>>(out);
}

// round 12
// speedup vs baseline: 6.4693x; 1.0456x over previous
#include <cuda_runtime.h>
#include <cuda_bf16.h>
#include <math.h>

// ---------------- problem constants ----------------
#define VSZ   32000
#define ESZ   512
#define HSZ   1024
#define TXN   2048
#define TYN   512
#define G4    4096
#define MARGIN 0.03f

// ---------------- device scratch ----------------
// G layout: [blk(128)][t(2048)][gate(4)][ui(8)]
__device__ float g_G[(size_t)TXN * G4];
__device__ float g_seq[(size_t)TXN * HSZ];
__device__ unsigned g_owbf[(size_t)VSZ * HSZ / 2];   // bf16 out_w (65.5MB)
__device__ float g_h[2][HSZ];
__device__ float g_hlast[HSZ];
__device__ float g_f1[HSZ];
__device__ float g_hinit[HSZ];
__device__ float g_aw0[2][G4];
__device__ float g_d1f[HSZ];
__device__ unsigned long long g_amax[TYN - 1];
__device__ unsigned int g_bars[4];

// ---------------- helpers ----------------
__device__ __forceinline__ float wredsum(float v) {
#pragma unroll
    for (int o = 16; o; o >>= 1) v += __shfl_xor_sync(0xffffffffu, v, o);
    return v;
}
__device__ __forceinline__ double wredsum_d(double v) {
#pragma unroll
    for (int o = 16; o; o >>= 1) v += __shfl_xor_sync(0xffffffffu, v, o);
    return v;
}
__device__ __forceinline__ float bflo(unsigned u) { return __uint_as_float(u << 16); }
__device__ __forceinline__ float bfhi(unsigned u) { return __uint_as_float(u & 0xFFFF0000u); }

__device__ __forceinline__ unsigned long long mkkey(float v, int idx) {
    unsigned u = __float_as_uint(v);
    u = (u & 0x80000000u) ? ~u : (u | 0x80000000u);
    return ((unsigned long long)u << 32) |
           (unsigned long long)(0xFFFFFFFFu - (unsigned)idx);
}

__device__ __forceinline__ void gates4_f(float a0, float a1, float a2, float a3,
                                         float addv, int lane,
                                         float& i_, float& f_, float& g_, float& o_) {
    float asel = (lane == 0) ? a0 : (lane == 1) ? a1 : (lane == 2) ? a2 : a3;
    float gv = 0.0f;
    if (lane < 4) {
        float x = asel + addv;
        gv = (lane == 2) ? tanhf(x) : 1.0f / (1.0f + expf(-x));
    }
    i_ = __shfl_sync(0xffffffffu, gv, 0);
    f_ = __shfl_sync(0xffffffffu, gv, 1);
    g_ = __shfl_sync(0xffffffffu, gv, 2);
    o_ = __shfl_sync(0xffffffffu, gv, 3);
}

// release/acquire software grid barrier
__device__ __forceinline__ void gbar(unsigned int* cnt, unsigned int& epoch) {
    epoch += gridDim.x;
    __syncthreads();
    if (threadIdx.x == 0) {
        asm volatile("red.release.gpu.global.add.u32 [%0], %1;"
                     :: "l"(cnt), "r"(1u) : "memory");
        unsigned cur;
        do {
            asm volatile("ld.acquire.gpu.global.u32 %0, [%1];"
                         : "=r"(cur) : "l"(cnt) : "memory");
        } while ((int)(cur - epoch) < 0);
    }
    __syncthreads();
}

// ---------------- init ----------------
__global__ void init_kernel() {
    int i = threadIdx.x;
    if (i < 4) g_bars[i] = 0u;
    for (int j = i; j < TYN - 1; j += blockDim.x) g_amax[j] = 0ull;
}

// ---------------- out_w fp32 -> bf16 (one-time) ----------------
__global__ void conv_bf16(const float* __restrict__ w) {
    size_t i = (size_t)blockIdx.x * blockDim.x + threadIdx.x;
    float4 v = *(const float4*)(w + i * 4);
    unsigned b0 = (unsigned)__bfloat16_as_ushort(__float2bfloat16_rn(v.x)) |
                  ((unsigned)__bfloat16_as_ushort(__float2bfloat16_rn(v.y)) << 16);
    unsigned b1 = (unsigned)__bfloat16_as_ushort(__float2bfloat16_rn(v.z)) |
                  ((unsigned)__bfloat16_as_ushort(__float2bfloat16_rn(v.w)) << 16);
    g_owbf[i * 2] = b0;
    g_owbf[i * 2 + 1] = b1;
}

// ---------------- tiled GEMM (fp32) with block-major transposed output ----------------
template <int KDIM>
__global__ void gemm_nt(const float* __restrict__ A, const int* __restrict__ ridx,
                        const float* __restrict__ B, const float* __restrict__ bias,
                        float* __restrict__ C) {
    __shared__ float As[64][17];
    __shared__ float Bs[64][17];
    int tid = threadIdx.x;
    int m0 = blockIdx.y * 64, n0 = blockIdx.x * 64;
    int tx = tid & 15, ty = tid >> 4;
    int lrow = tid >> 2;
    int lk4 = (tid & 3) * 4;
    const float* arow = A + (size_t)(ridx ? ridx[m0 + lrow] : (m0 + lrow)) * KDIM;
    const float* brow = B + (size_t)(n0 + lrow) * KDIM;
    float acc[4][4] = {};
    for (int kb = 0; kb < KDIM; kb += 16) {
        float4 av = *(const float4*)(arow + kb + lk4);
        float4 bv = *(const float4*)(brow + kb + lk4);
        __syncthreads();
        As[lrow][lk4 + 0] = av.x; As[lrow][lk4 + 1] = av.y;
        As[lrow][lk4 + 2] = av.z; As[lrow][lk4 + 3] = av.w;
        Bs[lrow][lk4 + 0] = bv.x; Bs[lrow][lk4 + 1] = bv.y;
        Bs[lrow][lk4 + 2] = bv.z; Bs[lrow][lk4 + 3] = bv.w;
        __syncthreads();
#pragma unroll
        for (int kk = 0; kk < 16; kk++) {
            float a[4], b[4];
#pragma unroll
            for (int i = 0; i < 4; i++) a[i] = As[ty * 4 + i][kk];
#pragma unroll
            for (int j = 0; j < 4; j++) b[j] = Bs[tx * 4 + j][kk];
#pragma unroll
            for (int i = 0; i < 4; i++)
#pragma unroll
                for (int j = 0; j < 4; j++) acc[i][j] += a[i] * b[j];
        }
    }
    int nb = n0 + tx * 4;
    int gate = nb >> 10;
    int u = nb & 1023;
    int blk = u >> 3, ui = u & 7;
    float4 b4 = __ldg((const float4*)(bias + nb));
    float* cb = C + (size_t)blk * (TXN * 32) + gate * 8 + ui;
#pragma unroll
    for (int i = 0; i < 4; i++) {
        int m = m0 + ty * 4 + i;
        float4 v = make_float4(acc[i][0] + b4.x, acc[i][1] + b4.y,
                               acc[i][2] + b4.z, acc[i][3] + b4.w);
        *(float4*)(cb + (size_t)m * 32) = v;
    }
}

// ---------------- persistent encoder LSTM scan — REGISTER-resident Whh ----------------
// 128 blocks x 512 threads. 2 warps per unit (half-columns). Weight regs:
// wr[gate][j] covers columns half*512 + j*128 + lane*4 .. +3.
template <int WRITE_SEQ, int WRITE_LAST, int BARIDX>
__global__ void __launch_bounds__(512, 1)
enc_scan(const float* __restrict__ Whh, const float* __restrict__ G,
         float* __restrict__ seq) {
    __shared__ float sh[HSZ];
    __shared__ float spart[8][4];
    int tid = threadIdx.x, w = tid >> 5, lane = tid & 31;
    int ui = w >> 1, half = w & 1;
    int unit = blockIdx.x * 8 + ui;
    float4 wr[4][4];
#pragma unroll
    for (int g = 0; g < 4; g++) {
        const float* bg = Whh + (size_t)(g * 1024 + unit) * 1024 + half * 512;
#pragma unroll
        for (int j = 0; j < 4; j++)
            wr[g][j] = __ldg((const float4*)(bg + j * 128 + lane * 4));
    }
    if (blockIdx.x == 0)
        for (int i = tid; i < HSZ; i += blockDim.x) g_h[0][i] = 0.0f;
    unsigned int epoch = 0;
    unsigned int* bar = &g_bars[BARIDX];
    const float* gp = G + (size_t)blockIdx.x * (TXN * 32);
    gbar(bar, epoch);
    float c = 0.0f;
    int cur = 0;
    for (int t = 0; t < TXN; t++) {
        float addv = 0.0f;
        if (half == 0 && lane < 4) addv = __ldg(gp + t * 32 + lane * 8 + ui);
        if (tid == 256 && t + 16 < TXN)
            asm volatile("prefetch.global.L2 [%0];" :: "l"(gp + (t + 16) * 32));
        if (tid < 256)
            *(float4*)(sh + tid * 4) = __ldcg((const float4*)(&g_h[cur][tid * 4]));
        __syncthreads();
        float4 h4[4];
#pragma unroll
        for (int j = 0; j < 4; j++)
            h4[j] = *(float4*)(sh + half * 512 + j * 128 + lane * 4);
        float a0 = 0, a1 = 0, a2 = 0, a3 = 0;
#pragma unroll
        for (int j = 0; j < 4; j++) {
            a0 += wr[0][j].x * h4[j].x + wr[0][j].y * h4[j].y +
                  wr[0][j].z * h4[j].z + wr[0][j].w * h4[j].w;
            a1 += wr[1][j].x * h4[j].x + wr[1][j].y * h4[j].y +
                  wr[1][j].z * h4[j].z + wr[1][j].w * h4[j].w;
            a2 += wr[2][j].x * h4[j].x + wr[2][j].y * h4[j].y +
                  wr[2][j].z * h4[j].z + wr[2][j].w * h4[j].w;
            a3 += wr[3][j].x * h4[j].x + wr[3][j].y * h4[j].y +
                  wr[3][j].z * h4[j].z + wr[3][j].w * h4[j].w;
        }
        a0 = wredsum(a0); a1 = wredsum(a1); a2 = wredsum(a2); a3 = wredsum(a3);
        float asel = (lane == 0) ? a0 : (lane == 1) ? a1 : (lane == 2) ? a2 : a3;
        if (half == 1 && lane < 4) spart[ui][lane] = asel;
        __syncthreads();
        if (half == 0) {
            float gv = 0.0f;
            if (lane < 4) {
                float x = asel + spart[ui][lane] + addv;
                gv = (lane == 2) ? tanhf(x) : 1.0f / (1.0f + expf(-x));
            }
            float i_ = __shfl_sync(0xffffffffu, gv, 0);
            float f_ = __shfl_sync(0xffffffffu, gv, 1);
            float gg = __shfl_sync(0xffffffffu, gv, 2);
            float o_ = __shfl_sync(0xffffffffu, gv, 3);
            if (lane == 0) {
                c = f_ * c + i_ * gg;
                float h = o_ * tanhf(c);
                g_h[cur ^ 1][unit] = h;
                if (WRITE_SEQ) seq[(size_t)t * HSZ + unit] = h;
                if (WRITE_LAST && t == TXN - 1) g_hlast[unit] = h;
            }
        }
        gbar(bar, epoch);
        cur ^= 1;
    }
}

// ---------------- fc + relu (fp64, off hot path) ----------------
__global__ void fc_relu(const float* __restrict__ W, const float* __restrict__ b,
                        const float* __restrict__ in, float* __restrict__ out) {
    __shared__ double red[8];
    int r = blockIdx.x, tid = threadIdx.x, wid = tid >> 5, lane = tid & 31;
    const float* wr = W + (size_t)r * 1024;
    float4 w = __ldg((const float4*)(wr + tid * 4));
    float4 v = __ldg((const float4*)(in + tid * 4));
    double acc = (double)(w.x * v.x) + (double)(w.y * v.y) +
                 (double)(w.z * v.z) + (double)(w.w * v.w);
    acc = wredsum_d(acc);
    if (lane == 0) red[wid] = acc;
    __syncthreads();
    if (tid == 0) {
        double s = 0;
#pragma unroll
        for (int i = 0; i < 8; i++) s += red[i];
        double val = s + (double)__ldg(b + r);
        out[r] = (float)(val > 0.0 ? val : 0.0);
    }
}

// ---------------- persistent greedy decoder (unchanged from R10) ----------------
#define DECT 512
__global__ void __launch_bounds__(DECT, 1)
decoder_kernel(
    const float* __restrict__ dWih0, const float* __restrict__ dWhh0, const float* __restrict__ db0,
    const float* __restrict__ dWih1, const float* __restrict__ dWhh1, const float* __restrict__ db1,
    const float* __restrict__ outw, const float* __restrict__ outb,
    const int* __restrict__ y, float* __restrict__ out) {
    __shared__ float sh0[HSZ];
    __shared__ float sh1[HSZ];
    __shared__ float c0s[HSZ];
    __shared__ float wih0s[G4];
    __shared__ float b0s[G4];
    __shared__ unsigned long long skeys[16];
    int tid = threadIdx.x, wid = tid >> 5, lane = tid & 31;
    int unit = wid * gridDim.x + blockIdx.x;
    unsigned int epoch = 0;
    unsigned int* bar = &g_bars[2];

    for (int i = tid; i < G4; i += DECT) {
        wih0s[i] = __ldg(dWih0 + i);
        b0s[i] = __ldg(db0 + i);
    }
    for (int i = tid; i < HSZ; i += DECT) {
        float v = __ldg(&g_hinit[i]);
        c0s[i] = v;
        sh0[i] = v;
    }
    __syncthreads();

    float c1 = 0.0f;
    if (unit < HSZ) c1 = __ldg(&g_hinit[unit]);

    float ah1p0 = 0, ah1p1 = 0, ah1p2 = 0, ah1p3 = 0;
    if (unit < HSZ) {
        float w0 = 0, w1 = 0, w2 = 0, w3 = 0;
        const float* bh0 = dWhh0 + (size_t)unit * 1024;
        const float* bh1 = dWhh1 + (size_t)unit * 1024;
#pragma unroll
        for (int k = 0; k < 8; k++) {
            int j = (k * 32 + lane) << 2;
            float4 h4 = *(float4*)(sh0 + j);
            float4 w;
            w = __ldg((const float4*)(bh0 + j));
            w0 += w.x * h4.x + w.y * h4.y + w.z * h4.z + w.w * h4.w;
            w = __ldg((const float4*)(bh0 + (1 << 20) + j));
            w1 += w.x * h4.x + w.y * h4.y + w.z * h4.z + w.w * h4.w;
            w = __ldg((const float4*)(bh0 + (2 << 20) + j));
            w2 += w.x * h4.x + w.y * h4.y + w.z * h4.z + w.w * h4.w;
            w = __ldg((const float4*)(bh0 + (3 << 20) + j));
            w3 += w.x * h4.x + w.y * h4.y + w.z * h4.z + w.w * h4.w;
            w = __ldg((const float4*)(bh1 + j));
            ah1p0 += w.x * h4.x + w.y * h4.y + w.z * h4.z + w.w * h4.w;
            w = __ldg((const float4*)(bh1 + (1 << 20) + j));
            ah1p1 += w.x * h4.x + w.y * h4.y + w.z * h4.z + w.w * h4.w;
            w = __ldg((const float4*)(bh1 + (2 << 20) + j));
            ah1p2 += w.x * h4.x + w.y * h4.y + w.z * h4.z + w.w * h4.w;
            w = __ldg((const float4*)(bh1 + (3 << 20) + j));
            ah1p3 += w.x * h4.x + w.y * h4.y + w.z * h4.z + w.w * h4.w;
        }
        w0 = wredsum(w0); w1 = wredsum(w1); w2 = wredsum(w2); w3 = wredsum(w3);
        ah1p0 = wredsum(ah1p0); ah1p1 = wredsum(ah1p1);
        ah1p2 = wredsum(ah1p2); ah1p3 = wredsum(ah1p3);
        float wsel = (lane == 0) ? w0 : (lane == 1) ? w1 : (lane == 2) ? w2 : w3;
        if (lane < 4) g_aw0[0][lane * 1024 + unit] = wsel;
    }
    gbar(bar, epoch);

    float xt0 = (float)__ldg(&y[0]);
    int gw = blockIdx.x * 16 + wid, nw = gridDim.x * 16;

    for (int t = 0; t < TYN - 1; t++) {
        float xt;
        if (t == 0) xt = xt0;
        else {
            unsigned long long key = __ldcg(&g_amax[t - 1]);
            xt = (float)(0xFFFFFFFFu - (unsigned int)(key & 0xFFFFFFFFull));
        }
        // ---- phase A: replicated layer0 ----
        {
            const float* aw = &g_aw0[t & 1][0];
#pragma unroll
            for (int uu = 0; uu < 2; uu++) {
                int u = tid + uu * DECT;
                float x0 = __ldcg(aw + u)        + (wih0s[u] * xt        + b0s[u]);
                float x1 = __ldcg(aw + 1024 + u) + (wih0s[1024 + u] * xt + b0s[1024 + u]);
                float x2 = __ldcg(aw + 2048 + u) + (wih0s[2048 + u] * xt + b0s[2048 + u]);
                float x3 = __ldcg(aw + 3072 + u) + (wih0s[3072 + u] * xt + b0s[3072 + u]);
                float i_ = 1.0f / (1.0f + expf(-x0));
                float f_ = 1.0f / (1.0f + expf(-x1));
                float gg = tanhf(x2);
                float o_ = 1.0f / (1.0f + expf(-x3));
                float c = f_ * c0s[u] + i_ * gg;
                c0s[u] = c;
                sh0[u] = o_ * tanhf(c);
            }
        }
        __syncthreads();
        // ---- phase B ----
        if (unit < HSZ) {
            float ai0 = 0, ai1 = 0, ai2 = 0, ai3 = 0;
            float w0 = 0, w1 = 0, w2 = 0, w3 = 0;
            const float* bi = dWih1 + (size_t)unit * 1024;
            const float* bh0 = dWhh0 + (size_t)unit * 1024;
#pragma unroll
            for (int k = 0; k < 8; k++) {
                int j = (k * 32 + lane) << 2;
                float4 h4 = *(float4*)(sh0 + j);
                float4 w;
                w = __ldg((const float4*)(bi + j));
                ai0 += w.x * h4.x + w.y * h4.y + w.z * h4.z + w.w * h4.w;
                w = __ldg((const float4*)(bi + (1 << 20) + j));
                ai1 += w.x * h4.x + w.y * h4.y + w.z * h4.z + w.w * h4.w;
                w = __ldg((const float4*)(bi + (2 << 20) + j));
                ai2 += w.x * h4.x + w.y * h4.y + w.z * h4.z + w.w * h4.w;
                w = __ldg((const float4*)(bi + (3 << 20) + j));
                ai3 += w.x * h4.x + w.y * h4.y + w.z * h4.z + w.w * h4.w;
                w = __ldg((const float4*)(bh0 + j));
                w0 += w.x * h4.x + w.y * h4.y + w.z * h4.z + w.w * h4.w;
                w = __ldg((const float4*)(bh0 + (1 << 20) + j));
                w1 += w.x * h4.x + w.y * h4.y + w.z * h4.z + w.w * h4.w;
                w = __ldg((const float4*)(bh0 + (2 << 20) + j));
                w2 += w.x * h4.x + w.y * h4.y + w.z * h4.z + w.w * h4.w;
                w = __ldg((const float4*)(bh0 + (3 << 20) + j));
                w3 += w.x * h4.x + w.y * h4.y + w.z * h4.z + w.w * h4.w;
            }
            ai0 = wredsum(ai0); ai1 = wredsum(ai1); ai2 = wredsum(ai2); ai3 = wredsum(ai3);
            w0 = wredsum(w0); w1 = wredsum(w1); w2 = wredsum(w2); w3 = wredsum(w3);
            float wsel = (lane == 0) ? w0 : (lane == 1) ? w1 : (lane == 2) ? w2 : w3;
            if (lane < 4) g_aw0[(t + 1) & 1][lane * 1024 + unit] = wsel;
            float addv = 0.0f;
            if (lane < 4) {
                float ap = (lane == 0) ? ah1p0 : (lane == 1) ? ah1p1
                         : (lane == 2) ? ah1p2 : ah1p3;
                addv = ap + __ldg(db1 + unit + lane * 1024);
            }
            float i_, f_, gg, o_;
            gates4_f(ai0, ai1, ai2, ai3, addv, lane, i_, f_, gg, o_);
            if (lane == 0) {
                c1 = f_ * c1 + i_ * gg;
                g_d1f[unit] = o_ * tanhf(c1);
            }
        }
        gbar(bar, epoch);
        // ---- phase C ----
        if (tid < 256)
            *(float4*)(sh1 + tid * 4) = __ldcg((const float4*)(&g_d1f[tid * 4]));
        __syncthreads();
        if (unit < HSZ) {
            ah1p0 = 0; ah1p1 = 0; ah1p2 = 0; ah1p3 = 0;
            const float* bh1 = dWhh1 + (size_t)unit * 1024;
#pragma unroll
            for (int k = 0; k < 8; k++) {
                int j = (k * 32 + lane) << 2;
                float4 h4 = *(float4*)(sh1 + j);
                float4 w;
                w = __ldg((const float4*)(bh1 + j));
                ah1p0 += w.x * h4.x + w.y * h4.y + w.z * h4.z + w.w * h4.w;
                w = __ldg((const float4*)(bh1 + (1 << 20) + j));
                ah1p1 += w.x * h4.x + w.y * h4.y + w.z * h4.z + w.w * h4.w;
                w = __ldg((const float4*)(bh1 + (2 << 20) + j));
                ah1p2 += w.x * h4.x + w.y * h4.y + w.z * h4.z + w.w * h4.w;
                w = __ldg((const float4*)(bh1 + (3 << 20) + j));
                ah1p3 += w.x * h4.x + w.y * h4.y + w.z * h4.z + w.w * h4.w;
            }
            ah1p0 = wredsum(ah1p0); ah1p1 = wredsum(ah1p1);
            ah1p2 = wredsum(ah1p2); ah1p3 = wredsum(ah1p3);
        }
        float bestv = -INFINITY; int besti = 0;
        float* orow = out + (size_t)(t + 1) * VSZ;
        int r = gw;
        for (; r + nw < VSZ; r += 2 * nw) {
            int r2 = r + nw;
            const uint4* wr0 = (const uint4*)(g_owbf + (size_t)r * 512);
            const uint4* wr1 = (const uint4*)(g_owbf + (size_t)r2 * 512);
            float pA0 = 0, pA1 = 0, pB0 = 0, pB1 = 0;
#pragma unroll
            for (int k = 0; k < 4; k++) {
                int q = k * 32 + lane;
                uint4 wa = __ldcs(wr0 + q);
                uint4 wb = __ldcs(wr1 + q);
                float4 h0 = *(float4*)(sh1 + 8 * q);
                float4 h1 = *(float4*)(sh1 + 8 * q + 4);
                pA0 += bflo(wa.x) * h0.x + bfhi(wa.x) * h0.y + bflo(wa.y) * h0.z + bfhi(wa.y) * h0.w;
                pA1 += bflo(wa.z) * h1.x + bfhi(wa.z) * h1.y + bflo(wa.w) * h1.z + bfhi(wa.w) * h1.w;
                pB0 += bflo(wb.x) * h0.x + bfhi(wb.x) * h0.y + bflo(wb.y) * h0.z + bfhi(wb.y) * h0.w;
                pB1 += bflo(wb.z) * h1.x + bfhi(wb.z) * h1.y + bflo(wb.w) * h1.z + bfhi(wb.w) * h1.w;
            }
            float accA = wredsum(pA0 + pA1);
            float accB = wredsum(pB0 + pB1);
            if (lane == 0) {
                float lgA = accA + __ldg(outb + r);
                float lgB = accB + __ldg(outb + r2);
                orow[r] = lgA;
                orow[r2] = lgB;
                if (lgA > bestv) { bestv = lgA; besti = r; }
                if (lgB > bestv) { bestv = lgB; besti = r2; }
            }
        }
        if (r < VSZ) {
            const uint4* wr0 = (const uint4*)(g_owbf + (size_t)r * 512);
            float p0 = 0, p1 = 0;
#pragma unroll
            for (int k = 0; k < 4; k++) {
                int q = k * 32 + lane;
                uint4 wa = __ldcs(wr0 + q);
                float4 h0 = *(float4*)(sh1 + 8 * q);
                float4 h1 = *(float4*)(sh1 + 8 * q + 4);
                p0 += bflo(wa.x) * h0.x + bfhi(wa.x) * h0.y + bflo(wa.y) * h0.z + bfhi(wa.y) * h0.w;
                p1 += bflo(wa.z) * h1.x + bfhi(wa.z) * h1.y + bflo(wa.w) * h1.z + bfhi(wa.w) * h1.w;
            }
            float acc = wredsum(p0 + p1);
            if (lane == 0) {
                float lg = acc + __ldg(outb + r);
                orow[r] = lg;
                if (lg > bestv) { bestv = lg; besti = r; }
            }
        }
        {
            float thresh = __shfl_sync(0xffffffffu, bestv, 0) - MARGIN;
            unsigned long long bkey2 = 0ull;
            for (int rr = gw; rr < VSZ; rr += nw) {
                float lv = 0.0f;
                if (lane == 0) lv = orow[rr];
                lv = __shfl_sync(0xffffffffu, lv, 0);
                if (lv >= thresh) {
                    const float* wrf = outw + (size_t)rr * 1024;
                    float p0 = 0, p1 = 0;
#pragma unroll
                    for (int k = 0; k < 8; k += 2) {
                        int j0 = (k * 32 + lane) << 2;
                        int j1 = ((k + 1) * 32 + lane) << 2;
                        float4 wa0 = __ldg((const float4*)(wrf + j0));
                        float4 wa1 = __ldg((const float4*)(wrf + j1));
                        float4 h40 = *(float4*)(sh1 + j0);
                        float4 h41 = *(float4*)(sh1 + j1);
                        p0 += wa0.x * h40.x + wa0.y * h40.y + wa0.z * h40.z + wa0.w * h40.w;
                        p1 += wa1.x * h41.x + wa1.y * h41.y + wa1.z * h41.z + wa1.w * h41.w;
                    }
                    float accf = wredsum(p0 + p1);
                    if (lane == 0) {
                        float lgf = accf + __ldg(outb + rr);
                        orow[rr] = lgf;
                        unsigned long long kk = mkkey(lgf, rr);
                        if (kk > bkey2) bkey2 = kk;
                    }
                }
            }
            if (lane == 0) skeys[wid] = bkey2;
        }
        __syncthreads();
        if (tid == 0) {
            unsigned long long k0 = skeys[0];
#pragma unroll
            for (int w = 1; w < 16; w++) if (skeys[w] > k0) k0 = skeys[w];
            atomicMax(&g_amax[t], k0);
        }
        gbar(bar, epoch);
    }
}

// ---------------- final log_softmax over rows (in place) ----------------
__global__ void logsoftmax_kernel(float* __restrict__ out) {
    int row = blockIdx.x, tid = threadIdx.x, wid = tid >> 5, lane = tid & 31;
    float* p = out + (size_t)row * VSZ;
    if (row == 0) {
        float v = -(float)log((double)VSZ);
        for (int i = tid; i < VSZ; i += blockDim.x) p[i] = v;
        return;
    }
    __shared__ double redd[8];
    __shared__ float redf[8];
    __shared__ float bcf;
    __shared__ double bcd;
    float m = -INFINITY;
    for (int i = tid; i < VSZ; i += blockDim.x) m = fmaxf(m, p[i]);
#pragma unroll
    for (int o = 16; o; o >>= 1) m = fmaxf(m, __shfl_xor_sync(0xffffffffu, m, o));
    if (lane == 0) redf[wid] = m;
    __syncthreads();
    if (tid == 0) {
        float mm = redf[0];
#pragma unroll
        for (int i = 1; i < 8; i++) mm = fmaxf(mm, redf[i]);
        bcf = mm;
    }
    __syncthreads();
    m = bcf;
    double s = 0;
    for (int i = tid; i < VSZ; i += blockDim.x) s += (double)expf(p[i] - m);
    s = wredsum_d(s);
    if (lane == 0) redd[wid] = s;
    __syncthreads();
    if (tid == 0) {
        double ss = 0;
#pragma unroll
        for (int i = 0; i < 8; i++) ss += redd[i];
        bcd = (double)m + log(ss);
    }
    __syncthreads();
    double lse = bcd;
    for (int i = tid; i < VSZ; i += blockDim.x) p[i] = (float)((double)p[i] - lse);
}

// ---------------- launch ----------------
extern "C" void kernel_launch(void* const* d_in, const int* in_sizes, int n_in,
                              void* d_out, int out_size) {
    const int*   x     = (const int*)d_in[0];
    const int*   y     = (const int*)d_in[1];
    const float* emb   = (const float*)d_in[2];
    const float* eWih0 = (const float*)d_in[3];
    const float* eWhh0 = (const float*)d_in[4];
    const float* eb0   = (const float*)d_in[5];
    const float* eWih1 = (const float*)d_in[6];
    const float* eWhh1 = (const float*)d_in[7];
    const float* eb1   = (const float*)d_in[8];
    const float* fc1w  = (const float*)d_in[9];
    const float* fc1b  = (const float*)d_in[10];
    const float* fc2w  = (const float*)d_in[11];
    const float* fc2b  = (const float*)d_in[12];
    const float* dWih0 = (const float*)d_in[13];
    const float* dWhh0 = (const float*)d_in[14];
    const float* db0   = (const float*)d_in[15];
    const float* dWih1 = (const float*)d_in[16];
    const float* dWhh1 = (const float*)d_in[17];
    const float* db1   = (const float*)d_in[18];
    const float* outw  = (const float*)d_in[19];
    const float* outb  = (const float*)d_in[20];
    float* out = (float*)d_out;

    float *pG = nullptr, *pSeq = nullptr, *pF1 = nullptr, *pHinit = nullptr, *pHlast = nullptr;
    cudaGetSymbolAddress((void**)&pG, g_G);
    cudaGetSymbolAddress((void**)&pSeq, g_seq);
    cudaGetSymbolAddress((void**)&pF1, g_f1);
    cudaGetSymbolAddress((void**)&pHinit, g_hinit);
    cudaGetSymbolAddress((void**)&pHlast, g_hlast);

    int dev = 0, nsm = 148;
    cudaGetDevice(&dev);
    cudaDeviceGetAttribute(&nsm, cudaDevAttrMultiProcessorCount, dev);
    if (nsm < 128) nsm = 128;

    init_kernel<<<1, 512>>>();
    conv_bf16<<<VSZ * (HSZ / 4) / 256, 256>>>(outw);
    gemm_nt<ESZ><<<dim3(64, 32), 256>>>(emb, x, eWih0, eb0, pG);
    enc_scan<1, 0, 0><<<128, 512>>>(eWhh0, pG, pSeq);
    gemm_nt<HSZ><<<dim3(64, 32), 256>>>(pSeq, nullptr, eWih1, eb1, pG);
    enc_scan<0, 1, 1><<<128, 512>>>(eWhh1, pG, nullptr);
    fc_relu<<<1024, 256>>>(fc1w, fc1b, pHlast, pF1);
    fc_relu<<<1024, 256>>>(fc2w, fc2b, pF1, pHinit);
    decoder_kernel<<<nsm, DECT>>>(dWih0, dWhh0, db0, dWih1, dWhh1, db1, outw, outb, y, out);
    logsoftmax_kernel<<<TYN, 256>>>(out);
}